// round 2
// baseline (speedup 1.0000x reference)
#include <cuda_runtime.h>
#include <math.h>

// Problem constants
#define Bq   2
#define Lq   2048
#define Hq   1024
#define Eq   2048
#define Nq   16
#define Rq   64
#define TOK  (Bq*Lq)        // 4096 tokens
#define PC   96             // packed proj cols: 64 (delta) + 16 (B) + 16 (C)

// ---------------- device scratch (allocation-free) ----------------
__device__ float g_xn[TOK*Hq];       // layernormed input
__device__ float g_u[TOK*Eq];        // silu(u)
__device__ float g_gate[TOK*Eq];     // raw gate (pre-silu)
__device__ float g_P[TOK*PC];        // [delta_proj(64) | B(16) | C(16)]
__device__ float g_delta[TOK*Eq];    // softplus delta
__device__ float g_y[TOK*Eq];        // scan output, fused with u*D and silu(gate)
__device__ float g_Wcat[Eq*PC];
__device__ float g_bcat[PC];

// ---------------- LayerNorm ----------------
__global__ void ln_kernel(const float* __restrict__ x,
                          const float* __restrict__ gamma,
                          const float* __restrict__ beta) {
    int m = blockIdx.x;
    const float* row = x + (size_t)m*Hq;
    float s = 0.f, s2 = 0.f;
    for (int i = threadIdx.x; i < Hq; i += blockDim.x) {
        float v = row[i]; s += v; s2 += v*v;
    }
    __shared__ float sh[64];
    for (int o = 16; o; o >>= 1) {
        s  += __shfl_xor_sync(~0u, s,  o);
        s2 += __shfl_xor_sync(~0u, s2, o);
    }
    int wid = threadIdx.x >> 5, lane = threadIdx.x & 31;
    if (lane == 0) { sh[wid] = s; sh[32+wid] = s2; }
    __syncthreads();
    if (wid == 0) {
        int nw = blockDim.x >> 5;
        s  = (lane < nw) ? sh[lane]    : 0.f;
        s2 = (lane < nw) ? sh[32+lane] : 0.f;
        for (int o = 16; o; o >>= 1) {
            s  += __shfl_xor_sync(~0u, s,  o);
            s2 += __shfl_xor_sync(~0u, s2, o);
        }
        if (lane == 0) { sh[0] = s; sh[1] = s2; }
    }
    __syncthreads();
    float mu  = sh[0] * (1.f/Hq);
    float var = sh[1] * (1.f/Hq) - mu*mu;
    float inv = rsqrtf(var + 1e-5f);
    for (int i = threadIdx.x; i < Hq; i += blockDim.x) {
        g_xn[(size_t)m*Hq + i] = (row[i]-mu)*inv*gamma[i] + beta[i];
    }
}

// ---------------- pack W_delta|W_B|W_C ----------------
__global__ void pack_kernel(const float* __restrict__ Wd, const float* __restrict__ Wb,
                            const float* __restrict__ Wc, const float* __restrict__ bd,
                            const float* __restrict__ bb, const float* __restrict__ bc) {
    int i = blockIdx.x*blockDim.x + threadIdx.x;
    if (i < Eq*PC) {
        int k = i / PC, c = i % PC;
        float v;
        if (c < 64)      v = Wd[k*64 + c];
        else if (c < 80) v = Wb[k*16 + (c-64)];
        else             v = Wc[k*16 + (c-80)];
        g_Wcat[i] = v;
    }
    if (i < PC) {
        g_bcat[i] = (i < 64) ? bd[i] : ((i < 80) ? bb[i-64] : bc[i-80]);
    }
}

// ---------------- generic tiled fp32 GEMM with fused epilogues ----------------
enum { EPI_PLAIN = 0, EPI_SPLIT_SILU = 1, EPI_SOFTPLUS = 2, EPI_RES = 3 };

template<int EPI>
__global__ void __launch_bounds__(256)
gemm_kernel(const float* __restrict__ A, int lda,
            const float* __restrict__ W, int ldw,
            const float* __restrict__ bias,
            float* __restrict__ C, int ldc,
            const float* __restrict__ extra,   // gate buffer (SPLIT_SILU) or residual (RES)
            int M, int N, int K)
{
    const int BM = 128, BN = 128, BK = 16;
    __shared__ float As[BK][BM+4];
    __shared__ float Ws[BK][BN];
    int m0 = blockIdx.y*BM, n0 = blockIdx.x*BN;
    int tid = threadIdx.x;
    int tx = tid & 15, ty = tid >> 4;
    float acc[8][8] = {};

    for (int k0 = 0; k0 < K; k0 += BK) {
        #pragma unroll
        for (int i = tid; i < BM*BK; i += 256) {
            int r = i >> 4, c = i & 15;
            int gm = m0 + r, gk = k0 + c;
            As[c][r] = (gm < M && gk < K) ? A[(size_t)gm*lda + gk] : 0.f;
        }
        #pragma unroll
        for (int i = tid; i < BK*BN; i += 256) {
            int r = i >> 7, c = i & 127;
            int gk = k0 + r, gn = n0 + c;
            Ws[r][c] = (gk < K && gn < N) ? W[(size_t)gk*ldw + gn] : 0.f;
        }
        __syncthreads();
        #pragma unroll
        for (int kk = 0; kk < BK; kk++) {
            float a[8], w[8];
            #pragma unroll
            for (int i = 0; i < 8; i++) a[i] = As[kk][ty*8 + i];
            #pragma unroll
            for (int j = 0; j < 8; j++) w[j] = Ws[kk][tx*8 + j];
            #pragma unroll
            for (int i = 0; i < 8; i++)
                #pragma unroll
                for (int j = 0; j < 8; j++)
                    acc[i][j] = fmaf(a[i], w[j], acc[i][j]);
        }
        __syncthreads();
    }

    #pragma unroll
    for (int i = 0; i < 8; i++) {
        int gm = m0 + ty*8 + i;
        if (gm >= M) continue;
        #pragma unroll
        for (int j = 0; j < 8; j++) {
            int gn = n0 + tx*8 + j;
            if (gn >= N) continue;
            float v = acc[i][j] + bias[gn];
            if (EPI == EPI_PLAIN) {
                C[(size_t)gm*ldc + gn] = v;
            } else if (EPI == EPI_SPLIT_SILU) {
                if (gn < Eq) {
                    C[(size_t)gm*Eq + gn] = v / (1.f + expf(-v));   // silu(u)
                } else {
                    ((float*)extra)[(size_t)gm*Eq + (gn - Eq)] = v; // raw gate
                }
            } else if (EPI == EPI_SOFTPLUS) {
                C[(size_t)gm*ldc + gn] = (v > 20.f) ? v : log1pf(expf(v));
            } else { // EPI_RES
                C[(size_t)gm*ldc + gn] = v + extra[(size_t)gm*ldc + gn];
            }
        }
    }
}

// ---------------- selective scan ----------------
// One 16-lane group per (b,e) channel; one lane per state n.
// Fused epilogue: y = (C·h + u*D) * silu(gate)
__global__ void __launch_bounds__(128)
scan_kernel(const float* __restrict__ A_log, const float* __restrict__ Dv) {
    int warpId = threadIdx.x >> 5;
    int lane   = threadIdx.x & 31;
    int half   = lane >> 4;
    int n      = lane & 15;
    int c = blockIdx.x*8 + warpId*2 + half;   // global channel in [0, B*E)
    int b = c >> 11;                          // c / Eq
    int e = c & (Eq-1);

    float Aen = -__expf(A_log[e*Nq + n]);
    float De  = Dv[e];

    const float* dptr = g_delta + (size_t)b*Lq*Eq + e;
    const float* uptr = g_u     + (size_t)b*Lq*Eq + e;
    const float* gptr = g_gate  + (size_t)b*Lq*Eq + e;
    const float* pB   = g_P     + (size_t)b*Lq*PC + 64 + n;
    const float* pC   = g_P     + (size_t)b*Lq*PC + 80 + n;
    float*       yptr = g_y     + (size_t)b*Lq*Eq + e;

    float h = 0.f;
    #pragma unroll 2
    for (int t = 0; t < Lq; t++) {
        float d  = dptr[(size_t)t*Eq];
        float xv = uptr[(size_t)t*Eq];
        float Bt = pB[t*PC];
        float Ct = pC[t*PC];
        float da = __expf(d * Aen);
        h = fmaf(da, h, d * Bt * xv);
        float yp = Ct * h;
        yp += __shfl_xor_sync(~0u, yp, 8);
        yp += __shfl_xor_sync(~0u, yp, 4);
        yp += __shfl_xor_sync(~0u, yp, 2);
        yp += __shfl_xor_sync(~0u, yp, 1);
        if (n == 0) {
            float g  = gptr[(size_t)t*Eq];
            float yy = fmaf(xv, De, yp);
            yy *= g / (1.f + expf(-g));     // * silu(gate)
            yptr[(size_t)t*Eq] = yy;
        }
    }
}

// ---------------- launch ----------------
extern "C" void kernel_launch(void* const* d_in, const int* in_sizes, int n_in,
                              void* d_out, int out_size) {
    const float* x       = (const float*)d_in[0];
    const float* lng     = (const float*)d_in[1];
    const float* lnb     = (const float*)d_in[2];
    const float* W_in    = (const float*)d_in[3];
    const float* b_in    = (const float*)d_in[4];
    const float* W_delta = (const float*)d_in[5];
    const float* b_delta = (const float*)d_in[6];
    const float* W_dt    = (const float*)d_in[7];
    const float* b_dt    = (const float*)d_in[8];
    const float* W_B     = (const float*)d_in[9];
    const float* b_B     = (const float*)d_in[10];
    const float* W_C     = (const float*)d_in[11];
    const float* b_C     = (const float*)d_in[12];
    const float* A_log   = (const float*)d_in[13];
    const float* Dv      = (const float*)d_in[14];
    const float* W_out   = (const float*)d_in[15];
    const float* b_out   = (const float*)d_in[16];
    float* out = (float*)d_out;

    void *p_xn, *p_u, *p_gate, *p_P, *p_delta, *p_y, *p_Wcat, *p_bcat;
    cudaGetSymbolAddress(&p_xn,    g_xn);
    cudaGetSymbolAddress(&p_u,     g_u);
    cudaGetSymbolAddress(&p_gate,  g_gate);
    cudaGetSymbolAddress(&p_P,     g_P);
    cudaGetSymbolAddress(&p_delta, g_delta);
    cudaGetSymbolAddress(&p_y,     g_y);
    cudaGetSymbolAddress(&p_Wcat,  g_Wcat);
    cudaGetSymbolAddress(&p_bcat,  g_bcat);

    // 1) LayerNorm
    ln_kernel<<<TOK, 256>>>(x, lng, lnb);
    // 2) pack concatenated projection weight (independent of LN)
    pack_kernel<<<(Eq*PC + 255)/256, 256>>>(W_delta, W_B, W_C, b_delta, b_B, b_C);
    // 3) GEMM1: xn @ W_in -> silu(u), gate
    gemm_kernel<EPI_SPLIT_SILU><<<dim3(2*Eq/128, TOK/128), 256>>>(
        (const float*)p_xn, Hq, W_in, 2*Eq, b_in,
        (float*)p_u, Eq, (const float*)p_gate, TOK, 2*Eq, Hq);
    // 4) P = u @ Wcat  [tokens, 96]
    gemm_kernel<EPI_PLAIN><<<dim3(1, TOK/128), 256>>>(
        (const float*)p_u, Eq, (const float*)p_Wcat, PC, (const float*)p_bcat,
        (float*)p_P, PC, nullptr, TOK, PC, Eq);
    // 5) delta = softplus(P[:, :64] @ W_dt)
    gemm_kernel<EPI_SOFTPLUS><<<dim3(Eq/128, TOK/128), 256>>>(
        (const float*)p_P, PC, W_dt, Eq, b_dt,
        (float*)p_delta, Eq, nullptr, TOK, Eq, Rq);
    // 6) selective scan (fused +u*D and *silu(gate))
    scan_kernel<<<(Bq*Eq)/8, 128>>>(A_log, Dv);
    // 7) out = y @ W_out + b_out + residual
    gemm_kernel<EPI_RES><<<dim3(Hq/128, TOK/128), 256>>>(
        (const float*)p_y, Eq, W_out, Hq, b_out,
        out, Hq, x, TOK, Hq, Eq);
}

// round 3
// speedup vs baseline: 2.2717x; 2.2717x over previous
#include <cuda_runtime.h>
#include <math.h>
#include <stdint.h>

// Problem constants
#define Bq   2
#define Lq   2048
#define Hq   1024
#define Eq   2048
#define Nq   16
#define Rq   64
#define TOK  (Bq*Lq)        // 4096 tokens
#define PC   96             // packed proj cols: 64 (delta) + 16 (B) + 16 (C)

// ---------------- device scratch (allocation-free) ----------------
__device__ __align__(16) float g_xn[TOK*Hq];       // layernormed input (tf32-rounded)
__device__ __align__(16) float g_u[TOK*Eq];        // silu(u) (tf32-rounded)
__device__ __align__(16) float g_gate[TOK*Eq];     // silu(gate)
__device__ __align__(16) float g_P[TOK*PC];        // [delta_proj(64) | B(16) | C(16)] tf32-rounded
__device__ __align__(16) float g_delta[TOK*Eq];    // softplus delta
__device__ __align__(16) float g_y[TOK*Eq];        // scan output (tf32-rounded)
__device__ __align__(16) float g_Wcat[Eq*PC];      // packed proj weight (tf32-rounded)
__device__ float g_bcat[PC];
__device__ __align__(16) float g_Wr_in[Hq*2*Eq];   // tf32-rounded weights
__device__ __align__(16) float g_Wr_dt[Rq*Eq];
__device__ __align__(16) float g_Wr_out[Eq*Hq];

// round-to-nearest tf32
__device__ __forceinline__ float rtf(float x) {
    uint32_t u;
    asm("cvt.rna.tf32.f32 %0, %1;" : "=r"(u) : "f"(x));
    return __uint_as_float(u);
}

__device__ __forceinline__ uint32_t sptr(const void* p) {
    return (uint32_t)__cvta_generic_to_shared(p);
}

// ---------------- LayerNorm (writes tf32-rounded xn) ----------------
__global__ void ln_kernel(const float* __restrict__ x,
                          const float* __restrict__ gamma,
                          const float* __restrict__ beta) {
    int m = blockIdx.x;
    const float* row = x + (size_t)m*Hq;
    float s = 0.f, s2 = 0.f;
    for (int i = threadIdx.x; i < Hq; i += blockDim.x) {
        float v = row[i]; s += v; s2 += v*v;
    }
    __shared__ float sh[64];
    for (int o = 16; o; o >>= 1) {
        s  += __shfl_xor_sync(~0u, s,  o);
        s2 += __shfl_xor_sync(~0u, s2, o);
    }
    int wid = threadIdx.x >> 5, lane = threadIdx.x & 31;
    if (lane == 0) { sh[wid] = s; sh[32+wid] = s2; }
    __syncthreads();
    if (wid == 0) {
        int nw = blockDim.x >> 5;
        s  = (lane < nw) ? sh[lane]    : 0.f;
        s2 = (lane < nw) ? sh[32+lane] : 0.f;
        for (int o = 16; o; o >>= 1) {
            s  += __shfl_xor_sync(~0u, s,  o);
            s2 += __shfl_xor_sync(~0u, s2, o);
        }
        if (lane == 0) { sh[0] = s; sh[1] = s2; }
    }
    __syncthreads();
    float mu  = sh[0] * (1.f/Hq);
    float var = sh[1] * (1.f/Hq) - mu*mu;
    float inv = rsqrtf(var + 1e-5f);
    for (int i = threadIdx.x; i < Hq; i += blockDim.x) {
        g_xn[(size_t)m*Hq + i] = rtf((row[i]-mu)*inv*gamma[i] + beta[i]);
    }
}

// ---------------- weight prep: tf32-round big weights ----------------
__global__ void round_weights(const float* __restrict__ Win,
                              const float* __restrict__ Wdt,
                              const float* __restrict__ Wout) {
    const int n1 = Hq*2*Eq, n2 = Rq*Eq, n3 = Eq*Hq;
    for (int i = blockIdx.x*blockDim.x + threadIdx.x; i < n1 + n2 + n3;
         i += gridDim.x*blockDim.x) {
        if (i < n1)            g_Wr_in[i]       = rtf(Win[i]);
        else if (i < n1+n2)    g_Wr_dt[i-n1]    = rtf(Wdt[i-n1]);
        else                   g_Wr_out[i-n1-n2]= rtf(Wout[i-n1-n2]);
    }
}

// ---------------- pack W_delta|W_B|W_C (tf32-rounded) ----------------
__global__ void pack_kernel(const float* __restrict__ Wd, const float* __restrict__ Wb,
                            const float* __restrict__ Wc, const float* __restrict__ bd,
                            const float* __restrict__ bb, const float* __restrict__ bc) {
    int i = blockIdx.x*blockDim.x + threadIdx.x;
    if (i < Eq*PC) {
        int k = i / PC, c = i % PC;
        float v;
        if (c < 64)      v = Wd[k*64 + c];
        else if (c < 80) v = Wb[k*16 + (c-64)];
        else             v = Wc[k*16 + (c-80)];
        g_Wcat[i] = rtf(v);
    }
    if (i < PC) {
        g_bcat[i] = (i < 64) ? bd[i] : ((i < 80) ? bb[i-64] : bc[i-80]);
    }
}

// ---------------- tf32 tensor-core GEMM with fused epilogues ----------------
enum { EPI_PLAIN = 0, EPI_SPLIT_SILU = 1, EPI_SOFTPLUS = 2, EPI_RES = 3 };

#define MMA_TF32(c0,c1,c2,c3,a0,a1,a2,a3,b0,b1) \
    asm volatile("mma.sync.aligned.m16n8k8.row.col.f32.tf32.tf32.f32 " \
                 "{%0,%1,%2,%3},{%4,%5,%6,%7},{%8,%9},{%0,%1,%2,%3};" \
                 : "+f"(c0),"+f"(c1),"+f"(c2),"+f"(c3) \
                 : "r"(a0),"r"(a1),"r"(a2),"r"(a3),"r"(b0),"r"(b1))

template<int N> __device__ __forceinline__ void cp_wait() {
    asm volatile("cp.async.wait_group %0;" :: "n"(N));
}
__device__ __forceinline__ void cp_commit() {
    asm volatile("cp.async.commit_group;" ::);
}

template<int EPI>
__global__ void __launch_bounds__(256)
gemm_tc(const float* __restrict__ A, int lda,
        const float* __restrict__ W, int ldw,
        const float* __restrict__ bias,
        float* __restrict__ C, int ldc,
        float* __restrict__ extra,      // gate out (SPLIT_SILU) or residual in (RES)
        int M, int N, int K)
{
    const int BM = 128, BN = 128, BK = 16;
    __shared__ float As[2][BM][BK+4];   // stride 20: conflict-free frag loads
    __shared__ float Bs[2][BK][BN+8];   // stride 136: conflict-free frag loads

    const int tid  = threadIdx.x;
    const int lane = tid & 31;
    const int warp = tid >> 5;
    const int wr   = warp & 1;          // 2 warp rows x 64
    const int wc   = warp >> 1;         // 4 warp cols x 32
    const int m0   = blockIdx.y * BM;
    const int n0   = blockIdx.x * BN;

    // global->smem copy mapping
    const int ar = tid >> 2;            // A row (j adds 64)
    const int ac = (tid & 3) * 4;       // A col (float4)
    const int br = tid >> 5;            // B row (j adds 8)
    const int bc = (tid & 31) * 4;      // B col (float4)

    auto issue = [&](int it, int buf) {
        int k0 = it * BK;
        #pragma unroll
        for (int j = 0; j < 2; j++) {
            int r = ar + j*64;
            const float* src = A + (size_t)(m0 + r)*lda + k0 + ac;
            uint32_t dst = sptr(&As[buf][r][ac]);
            asm volatile("cp.async.ca.shared.global [%0], [%1], 16;\n"
                         :: "r"(dst), "l"(src));
        }
        #pragma unroll
        for (int j = 0; j < 2; j++) {
            int r = br + j*8;
            int gn = n0 + bc;
            const float* src = W + (size_t)(k0 + r)*ldw + gn;
            int sz = 16;
            if (gn >= N) { sz = 0; src = W; }
            uint32_t dst = sptr(&Bs[buf][r][bc]);
            asm volatile("cp.async.ca.shared.global [%0], [%1], 16, %2;\n"
                         :: "r"(dst), "l"(src), "r"(sz));
        }
    };

    float acc[4][4][4];
    #pragma unroll
    for (int i = 0; i < 4; i++)
        #pragma unroll
        for (int j = 0; j < 4; j++)
            #pragma unroll
            for (int k = 0; k < 4; k++) acc[i][j][k] = 0.f;

    const int nIter = K / BK;
    issue(0, 0);
    cp_commit();

    for (int it = 0; it < nIter; it++) {
        int buf = it & 1;
        if (it + 1 < nIter) {
            issue(it + 1, buf ^ 1);
            cp_commit();
            cp_wait<1>();
        } else {
            cp_wait<0>();
        }
        __syncthreads();

        #pragma unroll
        for (int kk = 0; kk < 2; kk++) {
            int kb = kk * 8;
            uint32_t af[4][4], bf[4][2];
            #pragma unroll
            for (int mt = 0; mt < 4; mt++) {
                int r = wr*64 + mt*16 + (lane >> 2);
                int kc = kb + (lane & 3);
                af[mt][0] = __float_as_uint(As[buf][r    ][kc]);
                af[mt][1] = __float_as_uint(As[buf][r + 8][kc]);
                af[mt][2] = __float_as_uint(As[buf][r    ][kc + 4]);
                af[mt][3] = __float_as_uint(As[buf][r + 8][kc + 4]);
            }
            #pragma unroll
            for (int nt = 0; nt < 4; nt++) {
                int cN = wc*32 + nt*8 + (lane >> 2);
                int kc = kb + (lane & 3);
                bf[nt][0] = __float_as_uint(Bs[buf][kc    ][cN]);
                bf[nt][1] = __float_as_uint(Bs[buf][kc + 4][cN]);
            }
            #pragma unroll
            for (int mt = 0; mt < 4; mt++)
                #pragma unroll
                for (int nt = 0; nt < 4; nt++)
                    MMA_TF32(acc[mt][nt][0], acc[mt][nt][1], acc[mt][nt][2], acc[mt][nt][3],
                             af[mt][0], af[mt][1], af[mt][2], af[mt][3],
                             bf[nt][0], bf[nt][1]);
        }
        __syncthreads();
    }

    // epilogue
    #pragma unroll
    for (int mt = 0; mt < 4; mt++) {
        #pragma unroll
        for (int nt = 0; nt < 4; nt++) {
            #pragma unroll
            for (int q = 0; q < 4; q++) {
                int gm = m0 + wr*64 + mt*16 + (lane >> 2) + ((q >= 2) ? 8 : 0);
                int gn = n0 + wc*32 + nt*8 + 2*(lane & 3) + (q & 1);
                if (gm >= M || gn >= N) continue;
                float v = acc[mt][nt][q] + bias[gn];
                if (EPI == EPI_PLAIN) {
                    C[(size_t)gm*ldc + gn] = rtf(v);
                } else if (EPI == EPI_SPLIT_SILU) {
                    float sv = v / (1.f + __expf(-v));
                    if (gn < Eq) C[(size_t)gm*Eq + gn] = rtf(sv);         // silu(u), tf32
                    else         extra[(size_t)gm*Eq + (gn - Eq)] = sv;   // silu(gate)
                } else if (EPI == EPI_SOFTPLUS) {
                    C[(size_t)gm*ldc + gn] = (v > 20.f) ? v : log1pf(__expf(v));
                } else { // EPI_RES
                    C[(size_t)gm*ldc + gn] = v + extra[(size_t)gm*ldc + gn];
                }
            }
        }
    }
}

// ---------------- selective scan ----------------
// One 16-lane group per (b,e) channel; one lane per state n.
// Fused epilogue: y = (C.h + u*D) * silu_gate   (gate already silu'd)
__global__ void __launch_bounds__(128)
scan_kernel(const float* __restrict__ A_log, const float* __restrict__ Dv) {
    int warpId = threadIdx.x >> 5;
    int lane   = threadIdx.x & 31;
    int half   = lane >> 4;
    int n      = lane & 15;
    int c = blockIdx.x*8 + warpId*2 + half;   // global channel in [0, B*E)
    int b = c >> 11;                          // c / Eq
    int e = c & (Eq-1);

    float Aen = -__expf(A_log[e*Nq + n]);
    float De  = Dv[e];

    const float* dptr = g_delta + (size_t)b*Lq*Eq + e;
    const float* uptr = g_u     + (size_t)b*Lq*Eq + e;
    const float* gptr = g_gate  + (size_t)b*Lq*Eq + e;
    const float* pB   = g_P     + (size_t)b*Lq*PC + 64 + n;
    const float* pC   = g_P     + (size_t)b*Lq*PC + 80 + n;
    float*       yptr = g_y     + (size_t)b*Lq*Eq + e;

    float h = 0.f;
    #pragma unroll 2
    for (int t = 0; t < Lq; t++) {
        float d  = dptr[(size_t)t*Eq];
        float xv = uptr[(size_t)t*Eq];
        float Bt = pB[t*PC];
        float Ct = pC[t*PC];
        float da = __expf(d * Aen);
        h = fmaf(da, h, d * Bt * xv);
        float yp = Ct * h;
        yp += __shfl_xor_sync(~0u, yp, 8);
        yp += __shfl_xor_sync(~0u, yp, 4);
        yp += __shfl_xor_sync(~0u, yp, 2);
        yp += __shfl_xor_sync(~0u, yp, 1);
        if (n == 0) {
            float g  = gptr[(size_t)t*Eq];     // silu(gate)
            float yy = fmaf(xv, De, yp) * g;
            yptr[(size_t)t*Eq] = rtf(yy);
        }
    }
}

// ---------------- launch ----------------
extern "C" void kernel_launch(void* const* d_in, const int* in_sizes, int n_in,
                              void* d_out, int out_size) {
    const float* x       = (const float*)d_in[0];
    const float* lng     = (const float*)d_in[1];
    const float* lnb     = (const float*)d_in[2];
    const float* W_in    = (const float*)d_in[3];
    const float* b_in    = (const float*)d_in[4];
    const float* W_delta = (const float*)d_in[5];
    const float* b_delta = (const float*)d_in[6];
    const float* W_dt    = (const float*)d_in[7];
    const float* b_dt    = (const float*)d_in[8];
    const float* W_B     = (const float*)d_in[9];
    const float* b_B     = (const float*)d_in[10];
    const float* W_C     = (const float*)d_in[11];
    const float* b_C     = (const float*)d_in[12];
    const float* A_log   = (const float*)d_in[13];
    const float* Dv      = (const float*)d_in[14];
    const float* W_out   = (const float*)d_in[15];
    const float* b_out   = (const float*)d_in[16];
    float* out = (float*)d_out;

    void *p_xn, *p_u, *p_gate, *p_P, *p_delta, *p_y, *p_Wcat, *p_bcat;
    void *p_Wr_in, *p_Wr_dt, *p_Wr_out;
    cudaGetSymbolAddress(&p_xn,     g_xn);
    cudaGetSymbolAddress(&p_u,      g_u);
    cudaGetSymbolAddress(&p_gate,   g_gate);
    cudaGetSymbolAddress(&p_P,      g_P);
    cudaGetSymbolAddress(&p_delta,  g_delta);
    cudaGetSymbolAddress(&p_y,      g_y);
    cudaGetSymbolAddress(&p_Wcat,   g_Wcat);
    cudaGetSymbolAddress(&p_bcat,   g_bcat);
    cudaGetSymbolAddress(&p_Wr_in,  g_Wr_in);
    cudaGetSymbolAddress(&p_Wr_dt,  g_Wr_dt);
    cudaGetSymbolAddress(&p_Wr_out, g_Wr_out);

    // weight prep (independent of LN)
    round_weights<<<1024, 256>>>(W_in, W_dt, W_out);
    pack_kernel<<<(Eq*PC + 255)/256, 256>>>(W_delta, W_B, W_C, b_delta, b_B, b_C);
    // 1) LayerNorm -> tf32 xn
    ln_kernel<<<TOK, 256>>>(x, lng, lnb);
    // 2) GEMM1: xn @ W_in -> silu(u) [tf32], silu(gate)
    gemm_tc<EPI_SPLIT_SILU><<<dim3(2*Eq/128, TOK/128), 256>>>(
        (const float*)p_xn, Hq, (const float*)p_Wr_in, 2*Eq, b_in,
        (float*)p_u, Eq, (float*)p_gate, TOK, 2*Eq, Hq);
    // 3) P = u @ Wcat  [tokens, 96]
    gemm_tc<EPI_PLAIN><<<dim3(1, TOK/128), 256>>>(
        (const float*)p_u, Eq, (const float*)p_Wcat, PC, (const float*)p_bcat,
        (float*)p_P, PC, nullptr, TOK, PC, Eq);
    // 4) delta = softplus(P[:, :64] @ W_dt)
    gemm_tc<EPI_SOFTPLUS><<<dim3(Eq/128, TOK/128), 256>>>(
        (const float*)p_P, PC, (const float*)p_Wr_dt, Eq, b_dt,
        (float*)p_delta, Eq, nullptr, TOK, Eq, Rq);
    // 5) selective scan (fused +u*D and *silu(gate))
    scan_kernel<<<(Bq*Eq)/8, 128>>>(A_log, Dv);
    // 6) out = y @ W_out + b_out + residual
    gemm_tc<EPI_RES><<<dim3(Hq/128, TOK/128), 256>>>(
        (const float*)p_y, Eq, (const float*)p_Wr_out, Hq, b_out,
        out, Hq, (float*)(uintptr_t)x, TOK, Hq, Eq);
}

// round 4
// speedup vs baseline: 2.5718x; 1.1321x over previous
#include <cuda_runtime.h>
#include <math.h>
#include <stdint.h>

// Problem constants
#define Bq   2
#define Lq   2048
#define Hq   1024
#define Eq   2048
#define Nq   16
#define Rq   64
#define TOK  (Bq*Lq)        // 4096 tokens
#define PC   96             // packed proj cols: 64 (delta) + 16 (B) + 16 (C)
#define KSPLIT 8            // split-K factor for P-GEMM

// ---------------- device scratch (allocation-free) ----------------
__device__ __align__(16) float g_xn[TOK*Hq];       // layernormed input (tf32-rounded)
__device__ __align__(16) float g_u[TOK*Eq];        // silu(u) (tf32-rounded)
__device__ __align__(16) float g_gate[TOK*Eq];     // silu(gate)
__device__ __align__(16) float g_P[TOK*PC];        // [delta_proj(64) | B(16) | C(16)]
__device__ __align__(16) float g_Ppart[KSPLIT*TOK*PC]; // split-K partials
__device__ __align__(16) float g_delta[TOK*Eq];    // softplus delta
__device__ __align__(16) float g_y[TOK*Eq];        // scan output
__device__ __align__(16) float g_Wcat[Eq*PC];      // packed proj weight (tf32-rounded)
__device__ float g_bcat[PC];
__device__ __align__(16) float g_Wr_in[Hq*2*Eq];   // tf32-rounded weights
__device__ __align__(16) float g_Wr_dt[Rq*Eq];
__device__ __align__(16) float g_Wr_out[Eq*Hq];

// round-to-nearest tf32
__device__ __forceinline__ float rtf(float x) {
    uint32_t u;
    asm("cvt.rna.tf32.f32 %0, %1;" : "=r"(u) : "f"(x));
    return __uint_as_float(u);
}

__device__ __forceinline__ uint32_t sptr(const void* p) {
    return (uint32_t)__cvta_generic_to_shared(p);
}

// ---------------- LayerNorm (writes tf32-rounded xn) ----------------
__global__ void ln_kernel(const float* __restrict__ x,
                          const float* __restrict__ gamma,
                          const float* __restrict__ beta) {
    int m = blockIdx.x;
    const float* row = x + (size_t)m*Hq;
    float s = 0.f, s2 = 0.f;
    for (int i = threadIdx.x; i < Hq; i += blockDim.x) {
        float v = row[i]; s += v; s2 += v*v;
    }
    __shared__ float sh[64];
    for (int o = 16; o; o >>= 1) {
        s  += __shfl_xor_sync(~0u, s,  o);
        s2 += __shfl_xor_sync(~0u, s2, o);
    }
    int wid = threadIdx.x >> 5, lane = threadIdx.x & 31;
    if (lane == 0) { sh[wid] = s; sh[32+wid] = s2; }
    __syncthreads();
    if (wid == 0) {
        int nw = blockDim.x >> 5;
        s  = (lane < nw) ? sh[lane]    : 0.f;
        s2 = (lane < nw) ? sh[32+lane] : 0.f;
        for (int o = 16; o; o >>= 1) {
            s  += __shfl_xor_sync(~0u, s,  o);
            s2 += __shfl_xor_sync(~0u, s2, o);
        }
        if (lane == 0) { sh[0] = s; sh[1] = s2; }
    }
    __syncthreads();
    float mu  = sh[0] * (1.f/Hq);
    float var = sh[1] * (1.f/Hq) - mu*mu;
    float inv = rsqrtf(var + 1e-5f);
    for (int i = threadIdx.x; i < Hq; i += blockDim.x) {
        g_xn[(size_t)m*Hq + i] = rtf((row[i]-mu)*inv*gamma[i] + beta[i]);
    }
}

// ---------------- weight prep: tf32-round big weights (vectorized) ----------------
__global__ void round_weights(const float4* __restrict__ Win,
                              const float4* __restrict__ Wdt,
                              const float4* __restrict__ Wout) {
    const int n1 = Hq*2*Eq/4, n2 = Rq*Eq/4, n3 = Eq*Hq/4;
    float4* o1 = (float4*)g_Wr_in;
    float4* o2 = (float4*)g_Wr_dt;
    float4* o3 = (float4*)g_Wr_out;
    for (int i = blockIdx.x*blockDim.x + threadIdx.x; i < n1 + n2 + n3;
         i += gridDim.x*blockDim.x) {
        const float4* src; float4* dst; int j;
        if (i < n1)         { src = Win;  dst = o1; j = i; }
        else if (i < n1+n2) { src = Wdt;  dst = o2; j = i-n1; }
        else                { src = Wout; dst = o3; j = i-n1-n2; }
        float4 v = src[j];
        v.x = rtf(v.x); v.y = rtf(v.y); v.z = rtf(v.z); v.w = rtf(v.w);
        dst[j] = v;
    }
}

// ---------------- pack W_delta|W_B|W_C (tf32-rounded) ----------------
__global__ void pack_kernel(const float* __restrict__ Wd, const float* __restrict__ Wb,
                            const float* __restrict__ Wc, const float* __restrict__ bd,
                            const float* __restrict__ bb, const float* __restrict__ bc) {
    int i = blockIdx.x*blockDim.x + threadIdx.x;
    if (i < Eq*PC) {
        int k = i / PC, c = i % PC;
        float v;
        if (c < 64)      v = Wd[k*64 + c];
        else if (c < 80) v = Wb[k*16 + (c-64)];
        else             v = Wc[k*16 + (c-80)];
        g_Wcat[i] = rtf(v);
    }
    if (i < PC) {
        g_bcat[i] = (i < 64) ? bd[i] : ((i < 80) ? bb[i-64] : bc[i-80]);
    }
}

// ---------------- split-K reduction for P ----------------
__global__ void reduceP_kernel() {
    int i = blockIdx.x*blockDim.x + threadIdx.x;
    if (i >= TOK*PC) return;
    float s = g_bcat[i % PC];
    #pragma unroll
    for (int z = 0; z < KSPLIT; z++) s += g_Ppart[(size_t)z*TOK*PC + i];
    g_P[i] = s;
}

// ---------------- tf32 tensor-core GEMM, 3-stage pipeline, fused epilogues ----
enum { EPI_SPLIT_SILU = 1, EPI_SOFTPLUS = 2, EPI_RES = 3, EPI_PART = 4 };

#define MMA_TF32(c0,c1,c2,c3,a0,a1,a2,a3,b0,b1) \
    asm volatile("mma.sync.aligned.m16n8k8.row.col.f32.tf32.tf32.f32 " \
                 "{%0,%1,%2,%3},{%4,%5,%6,%7},{%8,%9},{%0,%1,%2,%3};" \
                 : "+f"(c0),"+f"(c1),"+f"(c2),"+f"(c3) \
                 : "r"(a0),"r"(a1),"r"(a2),"r"(a3),"r"(b0),"r"(b1))

template<int N> __device__ __forceinline__ void cp_wait() {
    asm volatile("cp.async.wait_group %0;" :: "n"(N));
}
__device__ __forceinline__ void cp_commit() {
    asm volatile("cp.async.commit_group;" ::);
}

#define BM 128
#define BN 128
#define BK 16
#define NSTAGE 3
#define AS_LD (BK+4)    // 20
#define BS_LD (BN+8)    // 136
#define SMEM_BYTES (NSTAGE*(BM*AS_LD + BK*BS_LD)*4)

template<int EPI>
__global__ void __launch_bounds__(256)
gemm_tc(const float* __restrict__ A, int lda,
        const float* __restrict__ W, int ldw,
        const float* __restrict__ bias,
        float* __restrict__ C, int ldc,
        float* __restrict__ extra,      // gate out (SPLIT_SILU) or residual in (RES)
        int M, int N, int K, int Kchunk)
{
    extern __shared__ float smem[];
    float (*As)[BM][AS_LD] = (float(*)[BM][AS_LD])smem;
    float (*Bs)[BK][BS_LD] = (float(*)[BK][BS_LD])(smem + NSTAGE*BM*AS_LD);

    const int tid  = threadIdx.x;
    const int lane = tid & 31;
    const int warp = tid >> 5;
    const int wr   = warp & 1;          // 2 warp rows x 64
    const int wc   = warp >> 1;         // 4 warp cols x 32
    const int m0   = blockIdx.y * BM;
    const int n0   = blockIdx.x * BN;
    const int Koff = blockIdx.z * Kchunk;

    // global->smem copy mapping
    const int ar = tid >> 2;            // A row (j adds 64)
    const int ac = (tid & 3) * 4;       // A col (float4)
    const int br = tid >> 5;            // B row (j adds 8)
    const int bc = (tid & 31) * 4;      // B col (float4)

    auto issue = [&](int it, int buf) {
        int k0 = Koff + it * BK;
        #pragma unroll
        for (int j = 0; j < 2; j++) {
            int r = ar + j*64;
            const float* src = A + (size_t)(m0 + r)*lda + k0 + ac;
            uint32_t dst = sptr(&As[buf][r][ac]);
            asm volatile("cp.async.ca.shared.global [%0], [%1], 16;\n"
                         :: "r"(dst), "l"(src));
        }
        #pragma unroll
        for (int j = 0; j < 2; j++) {
            int r = br + j*8;
            int gn = n0 + bc;
            const float* src = W + (size_t)(k0 + r)*ldw + gn;
            int sz = 16;
            if (gn >= N) { sz = 0; src = W; }
            uint32_t dst = sptr(&Bs[buf][r][bc]);
            asm volatile("cp.async.ca.shared.global [%0], [%1], 16, %2;\n"
                         :: "r"(dst), "l"(src), "r"(sz));
        }
    };

    float acc[4][4][4];
    #pragma unroll
    for (int i = 0; i < 4; i++)
        #pragma unroll
        for (int j = 0; j < 4; j++)
            #pragma unroll
            for (int k = 0; k < 4; k++) acc[i][j][k] = 0.f;

    const int nIter = Kchunk / BK;

    // prologue: fill NSTAGE-1 stages
    #pragma unroll
    for (int s = 0; s < NSTAGE-1; s++) {
        if (s < nIter) issue(s, s);
        cp_commit();
    }

    for (int it = 0; it < nIter; it++) {
        cp_wait<NSTAGE-2>();
        __syncthreads();
        int buf = it % NSTAGE;

        #pragma unroll
        for (int kk = 0; kk < 2; kk++) {
            int kb = kk * 8;
            uint32_t af[4][4], bf[4][2];
            #pragma unroll
            for (int mt = 0; mt < 4; mt++) {
                int r = wr*64 + mt*16 + (lane >> 2);
                int kc = kb + (lane & 3);
                af[mt][0] = __float_as_uint(As[buf][r    ][kc]);
                af[mt][1] = __float_as_uint(As[buf][r + 8][kc]);
                af[mt][2] = __float_as_uint(As[buf][r    ][kc + 4]);
                af[mt][3] = __float_as_uint(As[buf][r + 8][kc + 4]);
            }
            #pragma unroll
            for (int nt = 0; nt < 4; nt++) {
                int cN = wc*32 + nt*8 + (lane >> 2);
                int kc = kb + (lane & 3);
                bf[nt][0] = __float_as_uint(Bs[buf][kc    ][cN]);
                bf[nt][1] = __float_as_uint(Bs[buf][kc + 4][cN]);
            }
            #pragma unroll
            for (int mt = 0; mt < 4; mt++)
                #pragma unroll
                for (int nt = 0; nt < 4; nt++)
                    MMA_TF32(acc[mt][nt][0], acc[mt][nt][1], acc[mt][nt][2], acc[mt][nt][3],
                             af[mt][0], af[mt][1], af[mt][2], af[mt][3],
                             bf[nt][0], bf[nt][1]);
        }

        int nx = it + NSTAGE - 1;
        if (nx < nIter) issue(nx, nx % NSTAGE);
        cp_commit();
    }

    // epilogue
    #pragma unroll
    for (int mt = 0; mt < 4; mt++) {
        #pragma unroll
        for (int nt = 0; nt < 4; nt++) {
            #pragma unroll
            for (int q = 0; q < 4; q++) {
                int gm = m0 + wr*64 + mt*16 + (lane >> 2) + ((q >= 2) ? 8 : 0);
                int gn = n0 + wc*32 + nt*8 + 2*(lane & 3) + (q & 1);
                if (gm >= M || gn >= N) continue;
                if (EPI == EPI_PART) {
                    // raw partial, bias added in reduction
                    C[(size_t)blockIdx.z*TOK*PC + (size_t)gm*ldc + gn] = acc[mt][nt][q];
                    continue;
                }
                float v = acc[mt][nt][q] + bias[gn];
                if (EPI == EPI_SPLIT_SILU) {
                    float sv = v / (1.f + __expf(-v));
                    if (gn < Eq) C[(size_t)gm*Eq + gn] = rtf(sv);         // silu(u), tf32
                    else         extra[(size_t)gm*Eq + (gn - Eq)] = sv;   // silu(gate)
                } else if (EPI == EPI_SOFTPLUS) {
                    C[(size_t)gm*ldc + gn] = (v > 20.f) ? v : log1pf(__expf(v));
                } else { // EPI_RES
                    C[(size_t)gm*ldc + gn] = v + extra[(size_t)gm*ldc + gn];
                }
            }
        }
    }
}

// ---------------- selective scan ----------------
// One 16-lane group per (b,e) channel; one lane per state n.
// Fused epilogue: y = (C.h + u*D) * silu_gate   (gate already silu'd)
__global__ void __launch_bounds__(128)
scan_kernel(const float* __restrict__ A_log, const float* __restrict__ Dv) {
    int warpId = threadIdx.x >> 5;
    int lane   = threadIdx.x & 31;
    int half   = lane >> 4;
    int n      = lane & 15;
    int c = blockIdx.x*8 + warpId*2 + half;   // global channel in [0, B*E)
    int b = c >> 11;                          // c / Eq
    int e = c & (Eq-1);

    float Aen = -__expf(A_log[e*Nq + n]);
    float De  = Dv[e];

    const float* dptr = g_delta + (size_t)b*Lq*Eq + e;
    const float* uptr = g_u     + (size_t)b*Lq*Eq + e;
    const float* gptr = g_gate  + (size_t)b*Lq*Eq + e;
    const float* pB   = g_P     + (size_t)b*Lq*PC + 64 + n;
    const float* pC   = g_P     + (size_t)b*Lq*PC + 80 + n;
    float*       yptr = g_y     + (size_t)b*Lq*Eq + e;

    float h = 0.f;
    #pragma unroll 4
    for (int t = 0; t < Lq; t++) {
        float d  = __ldg(dptr + (size_t)t*Eq);
        float xv = __ldg(uptr + (size_t)t*Eq);
        float Bt = __ldg(pB + t*PC);
        float Ct = __ldg(pC + t*PC);
        float da = __expf(d * Aen);
        h = fmaf(da, h, d * Bt * xv);
        float yp = Ct * h;
        yp += __shfl_xor_sync(~0u, yp, 8);
        yp += __shfl_xor_sync(~0u, yp, 4);
        yp += __shfl_xor_sync(~0u, yp, 2);
        yp += __shfl_xor_sync(~0u, yp, 1);
        if (n == 0) {
            float g  = __ldg(gptr + (size_t)t*Eq);   // silu(gate)
            float yy = fmaf(xv, De, yp) * g;
            yptr[(size_t)t*Eq] = rtf(yy);
        }
    }
}

// ---------------- launch ----------------
extern "C" void kernel_launch(void* const* d_in, const int* in_sizes, int n_in,
                              void* d_out, int out_size) {
    const float* x       = (const float*)d_in[0];
    const float* lng     = (const float*)d_in[1];
    const float* lnb     = (const float*)d_in[2];
    const float* W_in    = (const float*)d_in[3];
    const float* b_in    = (const float*)d_in[4];
    const float* W_delta = (const float*)d_in[5];
    const float* b_delta = (const float*)d_in[6];
    const float* W_dt    = (const float*)d_in[7];
    const float* b_dt    = (const float*)d_in[8];
    const float* W_B     = (const float*)d_in[9];
    const float* b_B     = (const float*)d_in[10];
    const float* W_C     = (const float*)d_in[11];
    const float* b_C     = (const float*)d_in[12];
    const float* A_log   = (const float*)d_in[13];
    const float* Dv      = (const float*)d_in[14];
    const float* W_out   = (const float*)d_in[15];
    const float* b_out   = (const float*)d_in[16];
    float* out = (float*)d_out;

    void *p_xn, *p_u, *p_gate, *p_P, *p_Ppart, *p_delta, *p_y, *p_Wcat, *p_bcat;
    void *p_Wr_in, *p_Wr_dt, *p_Wr_out;
    cudaGetSymbolAddress(&p_xn,     g_xn);
    cudaGetSymbolAddress(&p_u,      g_u);
    cudaGetSymbolAddress(&p_gate,   g_gate);
    cudaGetSymbolAddress(&p_P,      g_P);
    cudaGetSymbolAddress(&p_Ppart,  g_Ppart);
    cudaGetSymbolAddress(&p_delta,  g_delta);
    cudaGetSymbolAddress(&p_y,      g_y);
    cudaGetSymbolAddress(&p_Wcat,   g_Wcat);
    cudaGetSymbolAddress(&p_bcat,   g_bcat);
    cudaGetSymbolAddress(&p_Wr_in,  g_Wr_in);
    cudaGetSymbolAddress(&p_Wr_dt,  g_Wr_dt);
    cudaGetSymbolAddress(&p_Wr_out, g_Wr_out);

    static bool attr_done = false;
    if (!attr_done) {
        cudaFuncSetAttribute(gemm_tc<EPI_SPLIT_SILU>, cudaFuncAttributeMaxDynamicSharedMemorySize, SMEM_BYTES);
        cudaFuncSetAttribute(gemm_tc<EPI_SOFTPLUS>,   cudaFuncAttributeMaxDynamicSharedMemorySize, SMEM_BYTES);
        cudaFuncSetAttribute(gemm_tc<EPI_RES>,        cudaFuncAttributeMaxDynamicSharedMemorySize, SMEM_BYTES);
        cudaFuncSetAttribute(gemm_tc<EPI_PART>,       cudaFuncAttributeMaxDynamicSharedMemorySize, SMEM_BYTES);
        attr_done = true;
    }

    // weight prep (independent of LN)
    round_weights<<<512, 256>>>((const float4*)W_in, (const float4*)W_dt, (const float4*)W_out);
    pack_kernel<<<(Eq*PC + 255)/256, 256>>>(W_delta, W_B, W_C, b_delta, b_B, b_C);
    // 1) LayerNorm -> tf32 xn
    ln_kernel<<<TOK, 256>>>(x, lng, lnb);
    // 2) GEMM1: xn @ W_in -> silu(u) [tf32], silu(gate)
    gemm_tc<EPI_SPLIT_SILU><<<dim3(2*Eq/128, TOK/128), 256, SMEM_BYTES>>>(
        (const float*)p_xn, Hq, (const float*)p_Wr_in, 2*Eq, b_in,
        (float*)p_u, Eq, (float*)p_gate, TOK, 2*Eq, Hq, Hq);
    // 3) P partials = u @ Wcat  (split-K over z)
    gemm_tc<EPI_PART><<<dim3(1, TOK/128, KSPLIT), 256, SMEM_BYTES>>>(
        (const float*)p_u, Eq, (const float*)p_Wcat, PC, (const float*)p_bcat,
        (float*)p_Ppart, PC, nullptr, TOK, PC, Eq, Eq/KSPLIT);
    // 3b) reduce partials + bias -> P
    reduceP_kernel<<<(TOK*PC + 255)/256, 256>>>();
    // 4) delta = softplus(P[:, :64] @ W_dt)
    gemm_tc<EPI_SOFTPLUS><<<dim3(Eq/128, TOK/128), 256, SMEM_BYTES>>>(
        (const float*)p_P, PC, (const float*)p_Wr_dt, Eq, b_dt,
        (float*)p_delta, Eq, nullptr, TOK, Eq, Rq, Rq);
    // 5) selective scan (fused +u*D and *silu(gate))
    scan_kernel<<<(Bq*Eq)/8, 128>>>(A_log, Dv);
    // 6) out = y @ W_out + b_out + residual
    gemm_tc<EPI_RES><<<dim3(Hq/128, TOK/128), 256, SMEM_BYTES>>>(
        (const float*)p_y, Eq, (const float*)p_Wr_out, Hq, b_out,
        out, Hq, (float*)(uintptr_t)x, TOK, Hq, Eq, Eq);
}

// round 5
// speedup vs baseline: 5.3650x; 2.0861x over previous
#include <cuda_runtime.h>
#include <math.h>
#include <stdint.h>

// Problem constants
#define Bq   2
#define Lq   2048
#define Hq   1024
#define Eq   2048
#define Nq   16
#define Rq   64
#define TOK  (Bq*Lq)        // 4096 tokens
#define PC   96             // packed proj cols: 64 (delta) + 16 (B) + 16 (C)
#define KSPLIT 8            // split-K factor for P-GEMM
#define NCHUNK 32           // scan chunks
#define CT    (Lq/NCHUNK)   // 64 timesteps per chunk
#define NCHAN (Bq*Eq)       // 4096 channels

// ---------------- device scratch (allocation-free) ----------------
__device__ __align__(16) float g_xn[TOK*Hq];
__device__ __align__(16) float g_u[TOK*Eq];        // silu(u) (tf32-rounded)
__device__ __align__(16) float g_gate[TOK*Eq];     // silu(gate)
__device__ __align__(16) float g_P[TOK*PC];        // [delta_proj(64) | B(16) | C(16)]
__device__ __align__(16) float g_Ppart[KSPLIT*TOK*PC];
__device__ __align__(16) float g_delta[TOK*Eq];    // softplus delta
__device__ __align__(16) float g_y[TOK*Eq];
__device__ __align__(16) float g_Wcat[Eq*PC];
__device__ float g_bcat[PC];
__device__ __align__(16) float g_Wr_in[Hq*2*Eq];
__device__ __align__(16) float g_Wr_dt[Rq*Eq];
__device__ __align__(16) float g_Wr_out[Eq*Hq];
// chunked-scan state: [chunk][chan][n]
__device__ __align__(16) float g_ap [NCHUNK*NCHAN*Nq];
__device__ __align__(16) float g_c  [NCHUNK*NCHAN*Nq];
__device__ __align__(16) float g_hin[NCHUNK*NCHAN*Nq];

__device__ __forceinline__ float rtf(float x) {
    uint32_t u;
    asm("cvt.rna.tf32.f32 %0, %1;" : "=r"(u) : "f"(x));
    return __uint_as_float(u);
}
__device__ __forceinline__ uint32_t sptr(const void* p) {
    return (uint32_t)__cvta_generic_to_shared(p);
}

// ---------------- LayerNorm (writes tf32-rounded xn) ----------------
__global__ void ln_kernel(const float* __restrict__ x,
                          const float* __restrict__ gamma,
                          const float* __restrict__ beta) {
    int m = blockIdx.x;
    const float* row = x + (size_t)m*Hq;
    float s = 0.f, s2 = 0.f;
    for (int i = threadIdx.x; i < Hq; i += blockDim.x) {
        float v = row[i]; s += v; s2 += v*v;
    }
    __shared__ float sh[64];
    for (int o = 16; o; o >>= 1) {
        s  += __shfl_xor_sync(~0u, s,  o);
        s2 += __shfl_xor_sync(~0u, s2, o);
    }
    int wid = threadIdx.x >> 5, lane = threadIdx.x & 31;
    if (lane == 0) { sh[wid] = s; sh[32+wid] = s2; }
    __syncthreads();
    if (wid == 0) {
        int nw = blockDim.x >> 5;
        s  = (lane < nw) ? sh[lane]    : 0.f;
        s2 = (lane < nw) ? sh[32+lane] : 0.f;
        for (int o = 16; o; o >>= 1) {
            s  += __shfl_xor_sync(~0u, s,  o);
            s2 += __shfl_xor_sync(~0u, s2, o);
        }
        if (lane == 0) { sh[0] = s; sh[1] = s2; }
    }
    __syncthreads();
    float mu  = sh[0] * (1.f/Hq);
    float var = sh[1] * (1.f/Hq) - mu*mu;
    float inv = rsqrtf(var + 1e-5f);
    for (int i = threadIdx.x; i < Hq; i += blockDim.x) {
        g_xn[(size_t)m*Hq + i] = rtf((row[i]-mu)*inv*gamma[i] + beta[i]);
    }
}

// ---------------- weight prep ----------------
__global__ void round_weights(const float4* __restrict__ Win,
                              const float4* __restrict__ Wdt,
                              const float4* __restrict__ Wout) {
    const int n1 = Hq*2*Eq/4, n2 = Rq*Eq/4, n3 = Eq*Hq/4;
    float4* o1 = (float4*)g_Wr_in;
    float4* o2 = (float4*)g_Wr_dt;
    float4* o3 = (float4*)g_Wr_out;
    for (int i = blockIdx.x*blockDim.x + threadIdx.x; i < n1 + n2 + n3;
         i += gridDim.x*blockDim.x) {
        const float4* src; float4* dst; int j;
        if (i < n1)         { src = Win;  dst = o1; j = i; }
        else if (i < n1+n2) { src = Wdt;  dst = o2; j = i-n1; }
        else                { src = Wout; dst = o3; j = i-n1-n2; }
        float4 v = src[j];
        v.x = rtf(v.x); v.y = rtf(v.y); v.z = rtf(v.z); v.w = rtf(v.w);
        dst[j] = v;
    }
}

__global__ void pack_kernel(const float* __restrict__ Wd, const float* __restrict__ Wb,
                            const float* __restrict__ Wc, const float* __restrict__ bd,
                            const float* __restrict__ bb, const float* __restrict__ bc) {
    int i = blockIdx.x*blockDim.x + threadIdx.x;
    if (i < Eq*PC) {
        int k = i / PC, c = i % PC;
        float v;
        if (c < 64)      v = Wd[k*64 + c];
        else if (c < 80) v = Wb[k*16 + (c-64)];
        else             v = Wc[k*16 + (c-80)];
        g_Wcat[i] = rtf(v);
    }
    if (i < PC) {
        g_bcat[i] = (i < 64) ? bd[i] : ((i < 80) ? bb[i-64] : bc[i-80]);
    }
}

// ---------------- split-K reduction for P ----------------
__global__ void reduceP_kernel() {
    int i = blockIdx.x*blockDim.x + threadIdx.x;
    if (i >= TOK*PC) return;
    float s = g_bcat[i % PC];
    #pragma unroll
    for (int z = 0; z < KSPLIT; z++) s += g_Ppart[(size_t)z*TOK*PC + i];
    g_P[i] = s;
}

// ---------------- tf32 tensor-core GEMM, 4-stage pipeline ----------------
enum { EPI_SPLIT_SILU = 1, EPI_SOFTPLUS = 2, EPI_RES = 3, EPI_PART = 4 };

#define MMA_TF32(c0,c1,c2,c3,a0,a1,a2,a3,b0,b1) \
    asm volatile("mma.sync.aligned.m16n8k8.row.col.f32.tf32.tf32.f32 " \
                 "{%0,%1,%2,%3},{%4,%5,%6,%7},{%8,%9},{%0,%1,%2,%3};" \
                 : "+f"(c0),"+f"(c1),"+f"(c2),"+f"(c3) \
                 : "r"(a0),"r"(a1),"r"(a2),"r"(a3),"r"(b0),"r"(b1))

template<int N> __device__ __forceinline__ void cp_wait() {
    asm volatile("cp.async.wait_group %0;" :: "n"(N));
}
__device__ __forceinline__ void cp_commit() {
    asm volatile("cp.async.commit_group;" ::);
}

#define BM 128
#define BN 128
#define BK 16
#define NSTAGE 4
#define AS_LD (BK+4)    // 20
#define BS_LD (BN+8)    // 136
#define SMEM_BYTES (NSTAGE*(BM*AS_LD + BK*BS_LD)*4)

template<int EPI>
__global__ void __launch_bounds__(256)
gemm_tc(const float* __restrict__ A, int lda,
        const float* __restrict__ W, int ldw,
        const float* __restrict__ bias,
        float* __restrict__ C, int ldc,
        float* __restrict__ extra,
        int M, int N, int K, int Kchunk)
{
    extern __shared__ float smem[];
    float (*As)[BM][AS_LD] = (float(*)[BM][AS_LD])smem;
    float (*Bs)[BK][BS_LD] = (float(*)[BK][BS_LD])(smem + NSTAGE*BM*AS_LD);

    const int tid  = threadIdx.x;
    const int lane = tid & 31;
    const int warp = tid >> 5;
    const int wr   = warp & 1;
    const int wc   = warp >> 1;
    const int m0   = blockIdx.y * BM;
    const int n0   = blockIdx.x * BN;
    const int Koff = blockIdx.z * Kchunk;

    const int ar = tid >> 2;
    const int ac = (tid & 3) * 4;
    const int br = tid >> 5;
    const int bc = (tid & 31) * 4;

    auto issue = [&](int it, int buf) {
        int k0 = Koff + it * BK;
        #pragma unroll
        for (int j = 0; j < 2; j++) {
            int r = ar + j*64;
            const float* src = A + (size_t)(m0 + r)*lda + k0 + ac;
            uint32_t dst = sptr(&As[buf][r][ac]);
            asm volatile("cp.async.ca.shared.global [%0], [%1], 16;\n"
                         :: "r"(dst), "l"(src));
        }
        #pragma unroll
        for (int j = 0; j < 2; j++) {
            int r = br + j*8;
            int gn = n0 + bc;
            const float* src = W + (size_t)(k0 + r)*ldw + gn;
            int sz = 16;
            if (gn >= N) { sz = 0; src = W; }
            uint32_t dst = sptr(&Bs[buf][r][bc]);
            asm volatile("cp.async.ca.shared.global [%0], [%1], 16, %2;\n"
                         :: "r"(dst), "l"(src), "r"(sz));
        }
    };

    float acc[4][4][4];
    #pragma unroll
    for (int i = 0; i < 4; i++)
        #pragma unroll
        for (int j = 0; j < 4; j++)
            #pragma unroll
            for (int k = 0; k < 4; k++) acc[i][j][k] = 0.f;

    const int nIter = Kchunk / BK;

    #pragma unroll
    for (int s = 0; s < NSTAGE-1; s++) {
        if (s < nIter) issue(s, s);
        cp_commit();
    }

    for (int it = 0; it < nIter; it++) {
        cp_wait<NSTAGE-2>();
        __syncthreads();
        int buf = it % NSTAGE;

        #pragma unroll
        for (int kk = 0; kk < 2; kk++) {
            int kb = kk * 8;
            uint32_t af[4][4], bf[4][2];
            #pragma unroll
            for (int mt = 0; mt < 4; mt++) {
                int r = wr*64 + mt*16 + (lane >> 2);
                int kc = kb + (lane & 3);
                af[mt][0] = __float_as_uint(As[buf][r    ][kc]);
                af[mt][1] = __float_as_uint(As[buf][r + 8][kc]);
                af[mt][2] = __float_as_uint(As[buf][r    ][kc + 4]);
                af[mt][3] = __float_as_uint(As[buf][r + 8][kc + 4]);
            }
            #pragma unroll
            for (int nt = 0; nt < 4; nt++) {
                int cN = wc*32 + nt*8 + (lane >> 2);
                int kc = kb + (lane & 3);
                bf[nt][0] = __float_as_uint(Bs[buf][kc    ][cN]);
                bf[nt][1] = __float_as_uint(Bs[buf][kc + 4][cN]);
            }
            #pragma unroll
            for (int mt = 0; mt < 4; mt++)
                #pragma unroll
                for (int nt = 0; nt < 4; nt++)
                    MMA_TF32(acc[mt][nt][0], acc[mt][nt][1], acc[mt][nt][2], acc[mt][nt][3],
                             af[mt][0], af[mt][1], af[mt][2], af[mt][3],
                             bf[nt][0], bf[nt][1]);
        }

        int nx = it + NSTAGE - 1;
        if (nx < nIter) issue(nx, nx % NSTAGE);
        cp_commit();
    }

    #pragma unroll
    for (int mt = 0; mt < 4; mt++) {
        #pragma unroll
        for (int nt = 0; nt < 4; nt++) {
            #pragma unroll
            for (int q = 0; q < 4; q++) {
                int gm = m0 + wr*64 + mt*16 + (lane >> 2) + ((q >= 2) ? 8 : 0);
                int gn = n0 + wc*32 + nt*8 + 2*(lane & 3) + (q & 1);
                if (gm >= M || gn >= N) continue;
                if (EPI == EPI_PART) {
                    C[(size_t)blockIdx.z*TOK*PC + (size_t)gm*ldc + gn] = acc[mt][nt][q];
                    continue;
                }
                float v = acc[mt][nt][q] + bias[gn];
                if (EPI == EPI_SPLIT_SILU) {
                    float sv = v / (1.f + __expf(-v));
                    if (gn < Eq) C[(size_t)gm*Eq + gn] = rtf(sv);
                    else         extra[(size_t)gm*Eq + (gn - Eq)] = sv;
                } else if (EPI == EPI_SOFTPLUS) {
                    C[(size_t)gm*ldc + gn] = (v > 20.f) ? v : log1pf(__expf(v));
                } else { // EPI_RES
                    C[(size_t)gm*ldc + gn] = v + extra[(size_t)gm*ldc + gn];
                }
            }
        }
    }
}

// ---------------- chunked selective scan ----------------
// Thread = one channel (b,e), 16 states in registers.
// Warp = 32 consecutive e (coalesced d/x/g loads); grid covers 32 chunks.
#define LOG2E 1.4426950408889634f

// Pass 1: per-chunk local scan with h=0; emit (prod a, h_local_end) per state.
__global__ void __launch_bounds__(256)
scan_p1(const float* __restrict__ A_log) {
    int gw    = blockIdx.x*8 + (threadIdx.x >> 5);   // 4096 warps
    int lane  = threadIdx.x & 31;
    int egrp  = gw & 127;          // 128 groups of 32 channels
    int chunk = gw >> 7;           // 32 chunks
    int c = egrp*32 + lane;        // channel
    int b = c >> 11;
    int e = c & (Eq-1);
    int t0 = chunk * CT;

    float Aen[Nq];
    #pragma unroll
    for (int n = 0; n < Nq; n++)
        Aen[n] = -__expf(A_log[e*Nq + n]) * LOG2E;   // fold log2e for exp2f

    float h[Nq], ap[Nq];
    #pragma unroll
    for (int n = 0; n < Nq; n++) { h[n] = 0.f; ap[n] = 1.f; }

    const float* dp = g_delta + ((size_t)b*Lq + t0)*Eq + e;
    const float* up = g_u     + ((size_t)b*Lq + t0)*Eq + e;

    #pragma unroll 2
    for (int t = 0; t < CT; t++) {
        float d  = dp[(size_t)t*Eq];
        float xv = up[(size_t)t*Eq];
        float dx = d * xv;
        const float4* pB4 = (const float4*)(g_P + ((size_t)b*Lq + t0 + t)*PC + 64);
        #pragma unroll
        for (int q = 0; q < 4; q++) {
            float4 Bv = __ldg(pB4 + q);
            float bb[4] = {Bv.x, Bv.y, Bv.z, Bv.w};
            #pragma unroll
            for (int r = 0; r < 4; r++) {
                int n = q*4 + r;
                float da = exp2f(d * Aen[n]);
                ap[n] *= da;
                h[n] = fmaf(da, h[n], dx * bb[r]);
            }
        }
    }
    float4* apo = (float4*)(g_ap + ((size_t)chunk*NCHAN + c)*Nq);
    float4* co  = (float4*)(g_c  + ((size_t)chunk*NCHAN + c)*Nq);
    #pragma unroll
    for (int q = 0; q < 4; q++) {
        apo[q] = make_float4(ap[q*4], ap[q*4+1], ap[q*4+2], ap[q*4+3]);
        co[q]  = make_float4(h[q*4],  h[q*4+1],  h[q*4+2],  h[q*4+3]);
    }
}

// Pass 2: compose chunk summaries -> h_in per chunk. One thread per (chan,n).
__global__ void __launch_bounds__(256)
scan_p2() {
    int i = blockIdx.x*blockDim.x + threadIdx.x;   // [0, NCHAN*Nq)
    if (i >= NCHAN*Nq) return;
    float hin = 0.f;
    #pragma unroll
    for (int k = 0; k < NCHUNK; k++) {
        size_t idx = (size_t)k*NCHAN*Nq + i;
        g_hin[idx] = hin;
        hin = g_ap[idx]*hin + g_c[idx];
    }
}

// Pass 3: re-run local scan seeded with h_in; compute y with fused epilogue.
__global__ void __launch_bounds__(256)
scan_p3(const float* __restrict__ A_log, const float* __restrict__ Dv) {
    int gw    = blockIdx.x*8 + (threadIdx.x >> 5);
    int lane  = threadIdx.x & 31;
    int egrp  = gw & 127;
    int chunk = gw >> 7;
    int c = egrp*32 + lane;
    int b = c >> 11;
    int e = c & (Eq-1);
    int t0 = chunk * CT;

    float Aen[Nq];
    #pragma unroll
    for (int n = 0; n < Nq; n++)
        Aen[n] = -__expf(A_log[e*Nq + n]) * LOG2E;
    float De = Dv[e];

    float h[Nq];
    const float4* hi = (const float4*)(g_hin + ((size_t)chunk*NCHAN + c)*Nq);
    #pragma unroll
    for (int q = 0; q < 4; q++) {
        float4 v = hi[q];
        h[q*4] = v.x; h[q*4+1] = v.y; h[q*4+2] = v.z; h[q*4+3] = v.w;
    }

    const float* dp = g_delta + ((size_t)b*Lq + t0)*Eq + e;
    const float* up = g_u     + ((size_t)b*Lq + t0)*Eq + e;
    const float* gp = g_gate  + ((size_t)b*Lq + t0)*Eq + e;
    float*       yp = g_y     + ((size_t)b*Lq + t0)*Eq + e;

    #pragma unroll 2
    for (int t = 0; t < CT; t++) {
        float d  = dp[(size_t)t*Eq];
        float xv = up[(size_t)t*Eq];
        float dx = d * xv;
        const float4* pB4 = (const float4*)(g_P + ((size_t)b*Lq + t0 + t)*PC + 64);
        float y = 0.f;
        #pragma unroll
        for (int q = 0; q < 4; q++) {
            float4 Bv = __ldg(pB4 + q);
            float4 Cv = __ldg(pB4 + 4 + q);
            float bb[4] = {Bv.x, Bv.y, Bv.z, Bv.w};
            float cc[4] = {Cv.x, Cv.y, Cv.z, Cv.w};
            #pragma unroll
            for (int r = 0; r < 4; r++) {
                int n = q*4 + r;
                float da = exp2f(d * Aen[n]);
                h[n] = fmaf(da, h[n], dx * bb[r]);
                y = fmaf(cc[r], h[n], y);
            }
        }
        float g = gp[(size_t)t*Eq];                 // silu(gate)
        yp[(size_t)t*Eq] = rtf(fmaf(xv, De, y) * g);
    }
}

// ---------------- launch ----------------
extern "C" void kernel_launch(void* const* d_in, const int* in_sizes, int n_in,
                              void* d_out, int out_size) {
    const float* x       = (const float*)d_in[0];
    const float* lng     = (const float*)d_in[1];
    const float* lnb     = (const float*)d_in[2];
    const float* W_in    = (const float*)d_in[3];
    const float* b_in    = (const float*)d_in[4];
    const float* W_delta = (const float*)d_in[5];
    const float* b_delta = (const float*)d_in[6];
    const float* W_dt    = (const float*)d_in[7];
    const float* b_dt    = (const float*)d_in[8];
    const float* W_B     = (const float*)d_in[9];
    const float* b_B     = (const float*)d_in[10];
    const float* W_C     = (const float*)d_in[11];
    const float* b_C     = (const float*)d_in[12];
    const float* A_log   = (const float*)d_in[13];
    const float* Dv      = (const float*)d_in[14];
    const float* W_out   = (const float*)d_in[15];
    const float* b_out   = (const float*)d_in[16];
    float* out = (float*)d_out;

    void *p_xn, *p_u, *p_gate, *p_P, *p_Ppart, *p_delta, *p_y, *p_Wcat, *p_bcat;
    void *p_Wr_in, *p_Wr_dt, *p_Wr_out;
    cudaGetSymbolAddress(&p_xn,     g_xn);
    cudaGetSymbolAddress(&p_u,      g_u);
    cudaGetSymbolAddress(&p_gate,   g_gate);
    cudaGetSymbolAddress(&p_P,      g_P);
    cudaGetSymbolAddress(&p_Ppart,  g_Ppart);
    cudaGetSymbolAddress(&p_delta,  g_delta);
    cudaGetSymbolAddress(&p_y,      g_y);
    cudaGetSymbolAddress(&p_Wcat,   g_Wcat);
    cudaGetSymbolAddress(&p_bcat,   g_bcat);
    cudaGetSymbolAddress(&p_Wr_in,  g_Wr_in);
    cudaGetSymbolAddress(&p_Wr_dt,  g_Wr_dt);
    cudaGetSymbolAddress(&p_Wr_out, g_Wr_out);

    static bool attr_done = false;
    if (!attr_done) {
        cudaFuncSetAttribute(gemm_tc<EPI_SPLIT_SILU>, cudaFuncAttributeMaxDynamicSharedMemorySize, SMEM_BYTES);
        cudaFuncSetAttribute(gemm_tc<EPI_SOFTPLUS>,   cudaFuncAttributeMaxDynamicSharedMemorySize, SMEM_BYTES);
        cudaFuncSetAttribute(gemm_tc<EPI_RES>,        cudaFuncAttributeMaxDynamicSharedMemorySize, SMEM_BYTES);
        cudaFuncSetAttribute(gemm_tc<EPI_PART>,       cudaFuncAttributeMaxDynamicSharedMemorySize, SMEM_BYTES);
        attr_done = true;
    }

    round_weights<<<512, 256>>>((const float4*)W_in, (const float4*)W_dt, (const float4*)W_out);
    pack_kernel<<<(Eq*PC + 255)/256, 256>>>(W_delta, W_B, W_C, b_delta, b_B, b_C);
    ln_kernel<<<TOK, 256>>>(x, lng, lnb);
    // GEMM1: xn @ W_in -> silu(u) [tf32], silu(gate)
    gemm_tc<EPI_SPLIT_SILU><<<dim3(2*Eq/128, TOK/128), 256, SMEM_BYTES>>>(
        (const float*)p_xn, Hq, (const float*)p_Wr_in, 2*Eq, b_in,
        (float*)p_u, Eq, (float*)p_gate, TOK, 2*Eq, Hq, Hq);
    // P partials = u @ Wcat (split-K), then reduce
    gemm_tc<EPI_PART><<<dim3(1, TOK/128, KSPLIT), 256, SMEM_BYTES>>>(
        (const float*)p_u, Eq, (const float*)p_Wcat, PC, (const float*)p_bcat,
        (float*)p_Ppart, PC, nullptr, TOK, PC, Eq, Eq/KSPLIT);
    reduceP_kernel<<<(TOK*PC + 255)/256, 256>>>();
    // delta = softplus(P[:, :64] @ W_dt)
    gemm_tc<EPI_SOFTPLUS><<<dim3(Eq/128, TOK/128), 256, SMEM_BYTES>>>(
        (const float*)p_P, PC, (const float*)p_Wr_dt, Eq, b_dt,
        (float*)p_delta, Eq, nullptr, TOK, Eq, Rq, Rq);
    // chunked selective scan (3 passes)
    scan_p1<<<(NCHAN/32)*NCHUNK/8, 256>>>(A_log);
    scan_p2<<<(NCHAN*Nq + 255)/256, 256>>>();
    scan_p3<<<(NCHAN/32)*NCHUNK/8, 256>>>(A_log, Dv);
    // out = y @ W_out + b_out + residual
    gemm_tc<EPI_RES><<<dim3(Hq/128, TOK/128), 256, SMEM_BYTES>>>(
        (const float*)p_y, Eq, (const float*)p_Wr_out, Hq, b_out,
        out, Hq, (float*)(uintptr_t)x, TOK, Hq, Eq, Eq);
}

// round 7
// speedup vs baseline: 7.0283x; 1.3100x over previous
#include <cuda_runtime.h>
#include <cuda_fp16.h>
#include <math.h>
#include <stdint.h>

// Problem constants
#define Bq   2
#define Lq   2048
#define Hq   1024
#define Eq   2048
#define Nq   16
#define Rq   64
#define TOK  (Bq*Lq)        // 4096 tokens
#define PC   96             // packed proj cols: 64 (delta) + 16 (B) + 16 (C)
#define PCP  128            // padded N for P-GEMM
#define KSPLIT 8
#define NCHUNK 32           // scan chunks
#define CT    (Lq/NCHUNK)   // 64 timesteps per chunk
#define NCHAN (Bq*Eq)       // 4096 channels

// ---------------- device scratch (allocation-free) ----------------
__device__ __align__(16) __half g_xn[TOK*Hq];      // layernormed input (fp16)
__device__ __align__(16) __half g_u[TOK*Eq];       // silu(u) fp16
__device__ __align__(16) __half g_gate[TOK*Eq];    // silu(gate) fp16
__device__ __align__(16) __half g_y[TOK*Eq];       // scan output fp16
__device__ __align__(16) float  g_P[TOK*PC];       // [delta_proj(64) | B(16) | C(16)] f32
__device__ __align__(16) __half g_Ph[TOK*64];      // delta-proj part, fp16 (GEMM input)
__device__ __align__(16) float  g_Ppart[KSPLIT*TOK*PC];
__device__ __align__(16) float  g_delta[TOK*Eq];   // softplus delta f32
__device__ __align__(16) __half g_WcatT[PCP*Eq];   // [delta|B|C]^T padded, fp16
__device__ float g_bcat[PC];
__device__ __align__(16) __half g_WtIn[2*Eq*Hq];   // W_in^T  [4096][1024] fp16
__device__ __align__(16) __half g_WtDt[Eq*Rq];     // W_dt^T  [2048][64]   fp16
__device__ __align__(16) __half g_WtOut[Hq*Eq];    // W_out^T [1024][2048] fp16
// chunked-scan state: [chunk][chan][n]
__device__ __align__(16) float g_ap [NCHUNK*NCHAN*Nq];
__device__ __align__(16) float g_c  [NCHUNK*NCHAN*Nq];
__device__ __align__(16) float g_hin[NCHUNK*NCHAN*Nq];

__device__ __forceinline__ uint32_t sptr(const void* p) {
    return (uint32_t)__cvta_generic_to_shared(p);
}

// ---------------- LayerNorm (writes fp16 xn) ----------------
__global__ void ln_kernel(const float* __restrict__ x,
                          const float* __restrict__ gamma,
                          const float* __restrict__ beta) {
    int m = blockIdx.x;
    const float* row = x + (size_t)m*Hq;
    float s = 0.f, s2 = 0.f;
    for (int i = threadIdx.x; i < Hq; i += blockDim.x) {
        float v = row[i]; s += v; s2 += v*v;
    }
    __shared__ float sh[64];
    for (int o = 16; o; o >>= 1) {
        s  += __shfl_xor_sync(~0u, s,  o);
        s2 += __shfl_xor_sync(~0u, s2, o);
    }
    int wid = threadIdx.x >> 5, lane = threadIdx.x & 31;
    if (lane == 0) { sh[wid] = s; sh[32+wid] = s2; }
    __syncthreads();
    if (wid == 0) {
        int nw = blockDim.x >> 5;
        s  = (lane < nw) ? sh[lane]    : 0.f;
        s2 = (lane < nw) ? sh[32+lane] : 0.f;
        for (int o = 16; o; o >>= 1) {
            s  += __shfl_xor_sync(~0u, s,  o);
            s2 += __shfl_xor_sync(~0u, s2, o);
        }
        if (lane == 0) { sh[0] = s; sh[1] = s2; }
    }
    __syncthreads();
    float mu  = sh[0] * (1.f/Hq);
    float var = sh[1] * (1.f/Hq) - mu*mu;
    float inv = rsqrtf(var + 1e-5f);
    for (int i = threadIdx.x; i < Hq; i += blockDim.x) {
        g_xn[(size_t)m*Hq + i] = __float2half_rn((row[i]-mu)*inv*gamma[i] + beta[i]);
    }
}

// ---------------- tiled transpose to fp16: dst[c][r] = h(src[r][c]) ----------
__global__ void transpose_h(const float* __restrict__ src, __half* __restrict__ dst,
                            int R, int Cc) {
    __shared__ float t[32][33];
    int c0 = blockIdx.x*32, r0 = blockIdx.y*32;
    for (int i = threadIdx.y; i < 32; i += 8)
        t[i][threadIdx.x] = src[(size_t)(r0+i)*Cc + c0 + threadIdx.x];
    __syncthreads();
    for (int i = threadIdx.y; i < 32; i += 8)
        dst[(size_t)(c0+i)*R + r0 + threadIdx.x] = __float2half_rn(t[threadIdx.x][i]);
}

// ---------------- pack W_delta|W_B|W_C transposed+padded, fp16 --------------
__global__ void pack_kernel(const float* __restrict__ Wd, const float* __restrict__ Wb,
                            const float* __restrict__ Wc, const float* __restrict__ bd,
                            const float* __restrict__ bb, const float* __restrict__ bc) {
    int i = blockIdx.x*blockDim.x + threadIdx.x;
    if (i < PCP*Eq) {
        int c = i / Eq, k = i % Eq;
        float v = 0.f;
        if (c < 64)      v = Wd[k*64 + c];
        else if (c < 80) v = Wb[k*16 + (c-64)];
        else if (c < 96) v = Wc[k*16 + (c-80)];
        g_WcatT[i] = __float2half_rn(v);
    }
    if (i < PC) {
        g_bcat[i] = (i < 64) ? bd[i] : ((i < 80) ? bb[i-64] : bc[i-80]);
    }
}

// ---------------- split-K reduction for P (f32 + fp16 delta part) -----------
__global__ void reduceP_kernel() {
    int i = blockIdx.x*blockDim.x + threadIdx.x;
    if (i >= TOK*PC) return;
    int c = i % PC, m = i / PC;
    float s = g_bcat[c];
    #pragma unroll
    for (int z = 0; z < KSPLIT; z++) s += g_Ppart[(size_t)z*TOK*PC + i];
    g_P[i] = s;
    if (c < 64) g_Ph[(size_t)m*64 + c] = __float2half_rn(s);
}

// ================= fp16 m16n8k16 GEMM, 4-stage cp.async =====================
enum { EPI_SPLIT_SILU = 1, EPI_SOFTPLUS = 2, EPI_RES = 3, EPI_PART = 4 };

#define MMA_F16(c0,c1,c2,c3,a0,a1,a2,a3,b0,b1) \
    asm volatile("mma.sync.aligned.m16n8k16.row.col.f32.f16.f16.f32 " \
                 "{%0,%1,%2,%3},{%4,%5,%6,%7},{%8,%9},{%0,%1,%2,%3};" \
                 : "+f"(c0),"+f"(c1),"+f"(c2),"+f"(c3) \
                 : "r"(a0),"r"(a1),"r"(a2),"r"(a3),"r"(b0),"r"(b1))

template<int N> __device__ __forceinline__ void cp_wait() {
    asm volatile("cp.async.wait_group %0;" :: "n"(N));
}
__device__ __forceinline__ void cp_commit() {
    asm volatile("cp.async.commit_group;" ::);
}

#define HBM 128
#define HBN 128
#define HBK 32
#define HSTAGE 4
#define HLD 40                      // halves per row (32 + 8 pad) = 80 bytes
#define HSTG (HBM*HLD)              // halves per stage tile (5120)
#define H_SMEM (HSTAGE*HSTG*2*2)    // A + B regions, bytes (81920)

template<int EPI>
__global__ void __launch_bounds__(256, 2)
gemm_h(const __half* __restrict__ A, int lda,
       const __half* __restrict__ Bt, int ldb,    // [N][K] K-major
       const float* __restrict__ bias,
       void* __restrict__ Cv, int ldc,
       const float* __restrict__ resid,           // residual (RES)
       __half* __restrict__ gate,                 // gate out (SPLIT_SILU)
       int M, int N, int K, int Kchunk)
{
    extern __shared__ __half smh[];
    __half* Asm = smh;
    __half* Bsm = smh + HSTAGE*HSTG;
    const uint32_t aBase = sptr(Asm);
    const uint32_t bBase = sptr(Bsm);

    const int tid  = threadIdx.x;
    const int lane = tid & 31;
    const int warp = tid >> 5;
    const int wr   = warp & 1;          // 2 x 64 rows
    const int wc   = warp >> 1;         // 4 x 32 cols
    const int m0   = blockIdx.y * HBM;
    const int n0   = blockIdx.x * HBN;
    const int Koff = blockIdx.z * Kchunk;

    auto issue = [&](int it, int buf) {
        int k0 = Koff + it * HBK;
        #pragma unroll
        for (int j = 0; j < 2; j++) {
            int id = tid + j*256;
            int row = id >> 2, slot = id & 3;
            const __half* as = A  + (size_t)(m0 + row)*lda + k0 + slot*8;
            const __half* bs = Bt + (size_t)(n0 + row)*ldb + k0 + slot*8;
            asm volatile("cp.async.ca.shared.global [%0], [%1], 16;\n"
                         :: "r"(aBase + buf*(HSTG*2) + row*80 + slot*16), "l"(as));
            asm volatile("cp.async.ca.shared.global [%0], [%1], 16;\n"
                         :: "r"(bBase + buf*(HSTG*2) + row*80 + slot*16), "l"(bs));
        }
    };

    float acc[4][4][4];
    #pragma unroll
    for (int i = 0; i < 4; i++)
        #pragma unroll
        for (int j = 0; j < 4; j++)
            #pragma unroll
            for (int k = 0; k < 4; k++) acc[i][j][k] = 0.f;

    const int nIter = Kchunk / HBK;
    #pragma unroll
    for (int s = 0; s < HSTAGE-1; s++) {
        if (s < nIter) issue(s, s);
        cp_commit();
    }

    for (int it = 0; it < nIter; it++) {
        cp_wait<HSTAGE-2>();
        __syncthreads();
        // overlap next loads with this tile's MMAs
        int nx = it + HSTAGE - 1;
        if (nx < nIter) issue(nx, nx & (HSTAGE-1));
        cp_commit();

        int buf = it & (HSTAGE-1);
        const __half* At = Asm + buf*HSTG;
        const __half* Bm = Bsm + buf*HSTG;

        #pragma unroll
        for (int kk = 0; kk < 2; kk++) {
            int k0 = kk*16 + (lane & 3)*2;
            uint32_t af[4][4], bf[4][2];
            #pragma unroll
            for (int mt = 0; mt < 4; mt++) {
                int r = wr*64 + mt*16 + (lane >> 2);
                af[mt][0] = *(const uint32_t*)(At + r*HLD + k0);
                af[mt][1] = *(const uint32_t*)(At + (r+8)*HLD + k0);
                af[mt][2] = *(const uint32_t*)(At + r*HLD + k0 + 8);
                af[mt][3] = *(const uint32_t*)(At + (r+8)*HLD + k0 + 8);
            }
            #pragma unroll
            for (int nt = 0; nt < 4; nt++) {
                int n = wc*32 + nt*8 + (lane >> 2);
                bf[nt][0] = *(const uint32_t*)(Bm + n*HLD + k0);
                bf[nt][1] = *(const uint32_t*)(Bm + n*HLD + k0 + 8);
            }
            #pragma unroll
            for (int mt = 0; mt < 4; mt++)
                #pragma unroll
                for (int nt = 0; nt < 4; nt++)
                    MMA_F16(acc[mt][nt][0], acc[mt][nt][1], acc[mt][nt][2], acc[mt][nt][3],
                            af[mt][0], af[mt][1], af[mt][2], af[mt][3],
                            bf[nt][0], bf[nt][1]);
        }
    }

    // epilogue
    #pragma unroll
    for (int mt = 0; mt < 4; mt++) {
        #pragma unroll
        for (int nt = 0; nt < 4; nt++) {
            #pragma unroll
            for (int q = 0; q < 4; q++) {
                int gm = m0 + wr*64 + mt*16 + (lane >> 2) + ((q >= 2) ? 8 : 0);
                int gn = n0 + wc*32 + nt*8 + 2*(lane & 3) + (q & 1);
                float v = acc[mt][nt][q];
                if (EPI == EPI_PART) {
                    if (gn < N)
                        ((float*)Cv)[(size_t)blockIdx.z*TOK*PC + (size_t)gm*ldc + gn] = v;
                    continue;
                }
                v += bias[gn];
                if (EPI == EPI_SPLIT_SILU) {
                    float sv = v / (1.f + __expf(-v));
                    if (gn < Eq) ((__half*)Cv)[(size_t)gm*Eq + gn] = __float2half_rn(sv);
                    else         gate[(size_t)gm*Eq + gn - Eq]    = __float2half_rn(sv);
                } else if (EPI == EPI_SOFTPLUS) {
                    ((float*)Cv)[(size_t)gm*ldc + gn] = (v > 20.f) ? v : log1pf(__expf(v));
                } else { // EPI_RES
                    ((float*)Cv)[(size_t)gm*ldc + gn] = v + resid[(size_t)gm*ldc + gn];
                }
            }
        }
    }
}

// ---------------- chunked selective scan ----------------
#define LOG2E 1.4426950408889634f

__global__ void __launch_bounds__(256)
scan_p1(const float* __restrict__ A_log) {
    int gw    = blockIdx.x*8 + (threadIdx.x >> 5);
    int lane  = threadIdx.x & 31;
    int egrp  = gw & 127;
    int chunk = gw >> 7;
    int c = egrp*32 + lane;
    int b = c >> 11;
    int e = c & (Eq-1);
    int t0 = chunk * CT;

    float Aen[Nq];
    #pragma unroll
    for (int n = 0; n < Nq; n++)
        Aen[n] = -__expf(A_log[e*Nq + n]) * LOG2E;

    float h[Nq], ap[Nq];
    #pragma unroll
    for (int n = 0; n < Nq; n++) { h[n] = 0.f; ap[n] = 1.f; }

    const float*  dp = g_delta + ((size_t)b*Lq + t0)*Eq + e;
    const __half* up = g_u     + ((size_t)b*Lq + t0)*Eq + e;

    #pragma unroll 2
    for (int t = 0; t < CT; t++) {
        float d  = dp[(size_t)t*Eq];
        float xv = __half2float(up[(size_t)t*Eq]);
        float dx = d * xv;
        const float4* pB4 = (const float4*)(g_P + ((size_t)b*Lq + t0 + t)*PC + 64);
        #pragma unroll
        for (int q = 0; q < 4; q++) {
            float4 Bv = __ldg(pB4 + q);
            float bb[4] = {Bv.x, Bv.y, Bv.z, Bv.w};
            #pragma unroll
            for (int r = 0; r < 4; r++) {
                int n = q*4 + r;
                float da = exp2f(d * Aen[n]);
                ap[n] *= da;
                h[n] = fmaf(da, h[n], dx * bb[r]);
            }
        }
    }
    float4* apo = (float4*)(g_ap + ((size_t)chunk*NCHAN + c)*Nq);
    float4* co  = (float4*)(g_c  + ((size_t)chunk*NCHAN + c)*Nq);
    #pragma unroll
    for (int q = 0; q < 4; q++) {
        apo[q] = make_float4(ap[q*4], ap[q*4+1], ap[q*4+2], ap[q*4+3]);
        co[q]  = make_float4(h[q*4],  h[q*4+1],  h[q*4+2],  h[q*4+3]);
    }
}

__global__ void __launch_bounds__(256)
scan_p2() {
    int i = blockIdx.x*blockDim.x + threadIdx.x;
    if (i >= NCHAN*Nq) return;
    float hin = 0.f;
    #pragma unroll
    for (int k = 0; k < NCHUNK; k++) {
        size_t idx = (size_t)k*NCHAN*Nq + i;
        g_hin[idx] = hin;
        hin = g_ap[idx]*hin + g_c[idx];
    }
}

__global__ void __launch_bounds__(256)
scan_p3(const float* __restrict__ A_log, const float* __restrict__ Dv) {
    int gw    = blockIdx.x*8 + (threadIdx.x >> 5);
    int lane  = threadIdx.x & 31;
    int egrp  = gw & 127;
    int chunk = gw >> 7;
    int c = egrp*32 + lane;
    int b = c >> 11;
    int e = c & (Eq-1);
    int t0 = chunk * CT;

    float Aen[Nq];
    #pragma unroll
    for (int n = 0; n < Nq; n++)
        Aen[n] = -__expf(A_log[e*Nq + n]) * LOG2E;
    float De = Dv[e];

    float h[Nq];
    const float4* hi = (const float4*)(g_hin + ((size_t)chunk*NCHAN + c)*Nq);
    #pragma unroll
    for (int q = 0; q < 4; q++) {
        float4 v = hi[q];
        h[q*4] = v.x; h[q*4+1] = v.y; h[q*4+2] = v.z; h[q*4+3] = v.w;
    }

    const float*  dp = g_delta + ((size_t)b*Lq + t0)*Eq + e;
    const __half* up = g_u     + ((size_t)b*Lq + t0)*Eq + e;
    const __half* gp = g_gate  + ((size_t)b*Lq + t0)*Eq + e;
    __half*       yp = g_y     + ((size_t)b*Lq + t0)*Eq + e;

    #pragma unroll 2
    for (int t = 0; t < CT; t++) {
        float d  = dp[(size_t)t*Eq];
        float xv = __half2float(up[(size_t)t*Eq]);
        float dx = d * xv;
        const float4* pB4 = (const float4*)(g_P + ((size_t)b*Lq + t0 + t)*PC + 64);
        float y = 0.f;
        #pragma unroll
        for (int q = 0; q < 4; q++) {
            float4 Bv = __ldg(pB4 + q);
            float4 Cv = __ldg(pB4 + 4 + q);
            float bb[4] = {Bv.x, Bv.y, Bv.z, Bv.w};
            float cc[4] = {Cv.x, Cv.y, Cv.z, Cv.w};
            #pragma unroll
            for (int r = 0; r < 4; r++) {
                int n = q*4 + r;
                float da = exp2f(d * Aen[n]);
                h[n] = fmaf(da, h[n], dx * bb[r]);
                y = fmaf(cc[r], h[n], y);
            }
        }
        float g = __half2float(gp[(size_t)t*Eq]);
        yp[(size_t)t*Eq] = __float2half_rn(fmaf(xv, De, y) * g);
    }
}

// ---------------- launch ----------------
extern "C" void kernel_launch(void* const* d_in, const int* in_sizes, int n_in,
                              void* d_out, int out_size) {
    const float* x       = (const float*)d_in[0];
    const float* lng     = (const float*)d_in[1];
    const float* lnb     = (const float*)d_in[2];
    const float* W_in    = (const float*)d_in[3];
    const float* b_in    = (const float*)d_in[4];
    const float* W_delta = (const float*)d_in[5];
    const float* b_delta = (const float*)d_in[6];
    const float* W_dt    = (const float*)d_in[7];
    const float* b_dt    = (const float*)d_in[8];
    const float* W_B     = (const float*)d_in[9];
    const float* b_B     = (const float*)d_in[10];
    const float* W_C     = (const float*)d_in[11];
    const float* b_C     = (const float*)d_in[12];
    const float* A_log   = (const float*)d_in[13];
    const float* Dv      = (const float*)d_in[14];
    const float* W_out   = (const float*)d_in[15];
    const float* b_out   = (const float*)d_in[16];
    float* out = (float*)d_out;

    void *p_xn, *p_u, *p_gate, *p_P, *p_Ph, *p_Ppart, *p_delta, *p_y;
    void *p_WcatT, *p_WtIn, *p_WtDt, *p_WtOut;
    cudaGetSymbolAddress(&p_xn,    g_xn);
    cudaGetSymbolAddress(&p_u,     g_u);
    cudaGetSymbolAddress(&p_gate,  g_gate);
    cudaGetSymbolAddress(&p_P,     g_P);
    cudaGetSymbolAddress(&p_Ph,    g_Ph);
    cudaGetSymbolAddress(&p_Ppart, g_Ppart);
    cudaGetSymbolAddress(&p_delta, g_delta);
    cudaGetSymbolAddress(&p_y,     g_y);
    cudaGetSymbolAddress(&p_WcatT, g_WcatT);
    cudaGetSymbolAddress(&p_WtIn,  g_WtIn);
    cudaGetSymbolAddress(&p_WtDt,  g_WtDt);
    cudaGetSymbolAddress(&p_WtOut, g_WtOut);

    static bool attr_done = false;
    if (!attr_done) {
        cudaFuncSetAttribute(gemm_h<EPI_SPLIT_SILU>, cudaFuncAttributeMaxDynamicSharedMemorySize, H_SMEM);
        cudaFuncSetAttribute(gemm_h<EPI_SOFTPLUS>,   cudaFuncAttributeMaxDynamicSharedMemorySize, H_SMEM);
        cudaFuncSetAttribute(gemm_h<EPI_RES>,        cudaFuncAttributeMaxDynamicSharedMemorySize, H_SMEM);
        cudaFuncSetAttribute(gemm_h<EPI_PART>,       cudaFuncAttributeMaxDynamicSharedMemorySize, H_SMEM);
        attr_done = true;
    }

    // prep: fp16 transposed weights + packed proj weight
    transpose_h<<<dim3(2*Eq/32, Hq/32), dim3(32,8)>>>(W_in,  (__half*)p_WtIn,  Hq, 2*Eq);
    transpose_h<<<dim3(Hq/32,   Eq/32), dim3(32,8)>>>(W_out, (__half*)p_WtOut, Eq, Hq);
    transpose_h<<<dim3(Eq/32,   Rq/32), dim3(32,8)>>>(W_dt,  (__half*)p_WtDt,  Rq, Eq);
    pack_kernel<<<(PCP*Eq + 255)/256, 256>>>(W_delta, W_B, W_C, b_delta, b_B, b_C);
    // LayerNorm -> fp16 xn
    ln_kernel<<<TOK, 256>>>(x, lng, lnb);
    // GEMM1: xn @ W_in -> silu(u), silu(gate)  [fp16 in, f32 acc]
    gemm_h<EPI_SPLIT_SILU><<<dim3(2*Eq/128, TOK/128), 256, H_SMEM>>>(
        (const __half*)p_xn, Hq, (const __half*)p_WtIn, Hq, b_in,
        p_u, Eq, nullptr, (__half*)p_gate, TOK, 2*Eq, Hq, Hq);
    // P partials = u @ Wcat (split-K), reduce (+fp16 copy of delta part)
    gemm_h<EPI_PART><<<dim3(1, TOK/128, KSPLIT), 256, H_SMEM>>>(
        (const __half*)p_u, Eq, (const __half*)p_WcatT, Eq, nullptr,
        p_Ppart, PC, nullptr, nullptr, TOK, PC, Eq, Eq/KSPLIT);
    reduceP_kernel<<<(TOK*PC + 255)/256, 256>>>();
    // delta = softplus(Ph @ W_dt)
    gemm_h<EPI_SOFTPLUS><<<dim3(Eq/128, TOK/128), 256, H_SMEM>>>(
        (const __half*)p_Ph, 64, (const __half*)p_WtDt, Rq, b_dt,
        p_delta, Eq, nullptr, nullptr, TOK, Eq, Rq, Rq);
    // chunked selective scan
    scan_p1<<<(NCHAN/32)*NCHUNK/8, 256>>>(A_log);
    scan_p2<<<(NCHAN*Nq + 255)/256, 256>>>();
    scan_p3<<<(NCHAN/32)*NCHUNK/8, 256>>>(A_log, Dv);
    // out = y @ W_out + b_out + residual
    gemm_h<EPI_RES><<<dim3(Hq/128, TOK/128), 256, H_SMEM>>>(
        (const __half*)p_y, Eq, (const __half*)p_WtOut, Eq, b_out,
        out, Hq, x, nullptr, TOK, Hq, Eq, Eq);
}

// round 9
// speedup vs baseline: 7.6063x; 1.0822x over previous
#include <cuda_runtime.h>
#include <cuda_fp16.h>
#include <math.h>
#include <stdint.h>

// Problem constants
#define Bq   2
#define Lq   2048
#define Hq   1024
#define Eq   2048
#define Nq   16
#define Rq   64
#define TOK  (Bq*Lq)        // 4096 tokens
#define PC   96             // packed proj cols: 64 (delta) + 16 (B) + 16 (C)
#define PCP  128            // padded N for P-GEMM
#define KSPLIT 8
#define NCHUNK 32           // scan chunks
#define CT    (Lq/NCHUNK)   // 64 timesteps per chunk
#define NCHAN (Bq*Eq)       // 4096 channels

// ---------------- device scratch (allocation-free) ----------------
__device__ __align__(16) __half g_xn[TOK*Hq];      // layernormed input (fp16)
__device__ __align__(16) __half g_u[TOK*Eq];       // silu(u) fp16
__device__ __align__(16) __half g_gate[TOK*Eq];    // silu(gate) fp16
__device__ __align__(16) __half g_y[TOK*Eq];       // scan output fp16
__device__ __align__(16) float  g_P[TOK*PC];       // [delta_proj(64) | B(16) | C(16)] f32
__device__ __align__(16) __half g_Ph[TOK*64];      // delta-proj part, fp16 (GEMM input)
__device__ __align__(16) float  g_Ppart[KSPLIT*TOK*PC];
__device__ __align__(16) float  g_delta[TOK*Eq];   // softplus delta f32
__device__ __align__(16) __half g_WcatT[PCP*Eq];   // [delta|B|C]^T padded, fp16
__device__ float g_bcat[PC];
__device__ __align__(16) __half g_WtIn[2*Eq*Hq];   // W_in^T  [4096][1024] fp16
__device__ __align__(16) __half g_WtDt[Eq*Rq];     // W_dt^T  [2048][64]   fp16
__device__ __align__(16) __half g_WtOut[Hq*Eq];    // W_out^T [1024][2048] fp16
// chunked-scan state: [chunk][chan][n]
__device__ __align__(16) float g_ap [NCHUNK*NCHAN*Nq];
__device__ __align__(16) float g_c  [NCHUNK*NCHAN*Nq];
__device__ __align__(16) float g_hin[NCHUNK*NCHAN*Nq];

__device__ __forceinline__ uint32_t sptr(const void* p) {
    return (uint32_t)__cvta_generic_to_shared(p);
}

// ---------------- LayerNorm (writes fp16 xn) ----------------
__global__ void ln_kernel(const float* __restrict__ x,
                          const float* __restrict__ gamma,
                          const float* __restrict__ beta) {
    int m = blockIdx.x;
    const float* row = x + (size_t)m*Hq;
    float s = 0.f, s2 = 0.f;
    for (int i = threadIdx.x; i < Hq; i += blockDim.x) {
        float v = row[i]; s += v; s2 += v*v;
    }
    __shared__ float sh[64];
    for (int o = 16; o; o >>= 1) {
        s  += __shfl_xor_sync(~0u, s,  o);
        s2 += __shfl_xor_sync(~0u, s2, o);
    }
    int wid = threadIdx.x >> 5, lane = threadIdx.x & 31;
    if (lane == 0) { sh[wid] = s; sh[32+wid] = s2; }
    __syncthreads();
    if (wid == 0) {
        int nw = blockDim.x >> 5;
        s  = (lane < nw) ? sh[lane]    : 0.f;
        s2 = (lane < nw) ? sh[32+lane] : 0.f;
        for (int o = 16; o; o >>= 1) {
            s  += __shfl_xor_sync(~0u, s,  o);
            s2 += __shfl_xor_sync(~0u, s2, o);
        }
        if (lane == 0) { sh[0] = s; sh[1] = s2; }
    }
    __syncthreads();
    float mu  = sh[0] * (1.f/Hq);
    float var = sh[1] * (1.f/Hq) - mu*mu;
    float inv = rsqrtf(var + 1e-5f);
    for (int i = threadIdx.x; i < Hq; i += blockDim.x) {
        g_xn[(size_t)m*Hq + i] = __float2half_rn((row[i]-mu)*inv*gamma[i] + beta[i]);
    }
}

// ---------------- tiled transpose to fp16: dst[c][r] = h(src[r][c]) ----------
__global__ void transpose_h(const float* __restrict__ src, __half* __restrict__ dst,
                            int R, int Cc) {
    __shared__ float t[32][33];
    int c0 = blockIdx.x*32, r0 = blockIdx.y*32;
    for (int i = threadIdx.y; i < 32; i += 8)
        t[i][threadIdx.x] = src[(size_t)(r0+i)*Cc + c0 + threadIdx.x];
    __syncthreads();
    for (int i = threadIdx.y; i < 32; i += 8)
        dst[(size_t)(c0+i)*R + r0 + threadIdx.x] = __float2half_rn(t[threadIdx.x][i]);
}

// ---------------- pack W_delta|W_B|W_C transposed+padded, fp16 --------------
__global__ void pack_kernel(const float* __restrict__ Wd, const float* __restrict__ Wb,
                            const float* __restrict__ Wc, const float* __restrict__ bd,
                            const float* __restrict__ bb, const float* __restrict__ bc) {
    int i = blockIdx.x*blockDim.x + threadIdx.x;
    if (i < PCP*Eq) {
        int c = i / Eq, k = i % Eq;
        float v = 0.f;
        if (c < 64)      v = Wd[k*64 + c];
        else if (c < 80) v = Wb[k*16 + (c-64)];
        else if (c < 96) v = Wc[k*16 + (c-80)];
        g_WcatT[i] = __float2half_rn(v);
    }
    if (i < PC) {
        g_bcat[i] = (i < 64) ? bd[i] : ((i < 80) ? bb[i-64] : bc[i-80]);
    }
}

// ---------------- split-K reduction for P (f32 + fp16 delta part) -----------
__global__ void reduceP_kernel() {
    int i = blockIdx.x*blockDim.x + threadIdx.x;
    if (i >= TOK*PC) return;
    int c = i % PC, m = i / PC;
    float s = g_bcat[c];
    #pragma unroll
    for (int z = 0; z < KSPLIT; z++) s += g_Ppart[(size_t)z*TOK*PC + i];
    g_P[i] = s;
    if (c < 64) g_Ph[(size_t)m*64 + c] = __float2half_rn(s);
}

// ======== fp16 m16n8k16 GEMM, 64x64 warptiles, ldmatrix, 4-stage ============
enum { EPI_SPLIT_SILU = 1, EPI_SOFTPLUS = 2, EPI_RES = 3, EPI_PART = 4 };

#define MMA_F16(c0,c1,c2,c3,a0,a1,a2,a3,b0,b1) \
    asm volatile("mma.sync.aligned.m16n8k16.row.col.f32.f16.f16.f32 " \
                 "{%0,%1,%2,%3},{%4,%5,%6,%7},{%8,%9},{%0,%1,%2,%3};" \
                 : "+f"(c0),"+f"(c1),"+f"(c2),"+f"(c3) \
                 : "r"(a0),"r"(a1),"r"(a2),"r"(a3),"r"(b0),"r"(b1))

#define LDSM_X4(r0,r1,r2,r3,addr) \
    asm volatile("ldmatrix.sync.aligned.m8n8.x4.shared.b16 {%0,%1,%2,%3}, [%4];" \
                 : "=r"(r0),"=r"(r1),"=r"(r2),"=r"(r3) : "r"(addr))

template<int N> __device__ __forceinline__ void cp_wait() {
    asm volatile("cp.async.wait_group %0;" :: "n"(N));
}
__device__ __forceinline__ void cp_commit() {
    asm volatile("cp.async.commit_group;" ::);
}

#define HBM 128
#define HBN 128
#define HBK 32
#define HSTAGE 4
#define HLD 40                      // halves per row (32 + 8 pad) = 80 bytes
#define HSTG (HBM*HLD)              // halves per stage tile (5120)
#define H_SMEM (HSTAGE*HSTG*2*2)    // A + B regions, bytes (81920)

template<int EPI>
__global__ void __launch_bounds__(128, 2)
gemm_h(const __half* __restrict__ A, int lda,
       const __half* __restrict__ Bt, int ldb,    // [N][K] K-major
       const float* __restrict__ bias,
       void* __restrict__ Cv, int ldc,
       const float* __restrict__ resid,           // residual (RES)
       __half* __restrict__ gate,                 // gate out (SPLIT_SILU)
       int M, int N, int K, int Kchunk)
{
    extern __shared__ __half smh[];
    __half* Asm = smh;
    __half* Bsm = smh + HSTAGE*HSTG;
    const uint32_t aBase = sptr(Asm);
    const uint32_t bBase = sptr(Bsm);

    const int tid  = threadIdx.x;
    const int lane = tid & 31;
    const int warp = tid >> 5;
    const int wr   = warp & 1;          // 2 x 64 rows
    const int wc   = warp >> 1;         // 2 x 64 cols
    const int m0   = blockIdx.y * HBM;
    const int n0   = blockIdx.x * HBN;
    const int Koff = blockIdx.z * Kchunk;

    // ldmatrix per-lane base offsets (in halves; *2 for bytes at use site)
    // A (16x16 per mt): lanes 0-15 rows, col 0; lanes 16-31 rows, col 8
    const uint32_t aRow = wr*64 + (lane & 15);
    const uint32_t aCol = (lane >> 4) * 8;
    // B (16 n-rows x 16 k-cols per ntp), NON-trans:
    // lanes 0-7: n0..n0+7 @k0 | 8-15: n0..n0+7 @k0+8 | 16-23: n0+8..15 @k0 | 24-31: @k0+8
    const uint32_t bRow = wc*64 + (lane & 7) + ((lane >> 4) << 3);
    const uint32_t bCol = ((lane >> 3) & 1) * 8;

    auto issue = [&](int it, int buf) {
        int k0 = Koff + it * HBK;
        #pragma unroll
        for (int j = 0; j < 4; j++) {
            int id = tid + j*128;
            int row = id >> 2, slot = id & 3;
            const __half* as = A  + (size_t)(m0 + row)*lda + k0 + slot*8;
            const __half* bs = Bt + (size_t)(n0 + row)*ldb + k0 + slot*8;
            asm volatile("cp.async.ca.shared.global [%0], [%1], 16;\n"
                         :: "r"(aBase + buf*(HSTG*2) + row*80 + slot*16), "l"(as));
            asm volatile("cp.async.ca.shared.global [%0], [%1], 16;\n"
                         :: "r"(bBase + buf*(HSTG*2) + row*80 + slot*16), "l"(bs));
        }
    };

    float acc[4][8][4];
    #pragma unroll
    for (int i = 0; i < 4; i++)
        #pragma unroll
        for (int j = 0; j < 8; j++)
            #pragma unroll
            for (int k = 0; k < 4; k++) acc[i][j][k] = 0.f;

    const int nIter = Kchunk / HBK;
    #pragma unroll
    for (int s = 0; s < HSTAGE-1; s++) {
        if (s < nIter) issue(s, s);
        cp_commit();
    }

    for (int it = 0; it < nIter; it++) {
        cp_wait<HSTAGE-2>();
        __syncthreads();
        int nx = it + HSTAGE - 1;
        if (nx < nIter) issue(nx, nx & (HSTAGE-1));
        cp_commit();

        int buf = it & (HSTAGE-1);
        uint32_t aB = aBase + buf*(HSTG*2);
        uint32_t bB = bBase + buf*(HSTG*2);

        #pragma unroll
        for (int kk = 0; kk < 2; kk++) {
            uint32_t af[4][4], bf[8][2];
            #pragma unroll
            for (int mt = 0; mt < 4; mt++) {
                uint32_t ad = aB + ((aRow + mt*16)*HLD + kk*16 + aCol)*2;
                LDSM_X4(af[mt][0], af[mt][1], af[mt][2], af[mt][3], ad);
            }
            #pragma unroll
            for (int ntp = 0; ntp < 4; ntp++) {
                uint32_t bd = bB + ((bRow + ntp*16)*HLD + kk*16 + bCol)*2;
                // matrices: 0 -> (n 0-7, k0-7)=bf[2ntp][0], 1 -> (n 0-7, k8-15)=bf[2ntp][1],
                //           2 -> (n 8-15, k0-7)=bf[2ntp+1][0], 3 -> (n 8-15, k8-15)=bf[2ntp+1][1]
                LDSM_X4(bf[2*ntp][0], bf[2*ntp][1], bf[2*ntp+1][0], bf[2*ntp+1][1], bd);
            }
            #pragma unroll
            for (int mt = 0; mt < 4; mt++)
                #pragma unroll
                for (int nt = 0; nt < 8; nt++)
                    MMA_F16(acc[mt][nt][0], acc[mt][nt][1], acc[mt][nt][2], acc[mt][nt][3],
                            af[mt][0], af[mt][1], af[mt][2], af[mt][3],
                            bf[nt][0], bf[nt][1]);
        }
    }

    // epilogue
    #pragma unroll
    for (int mt = 0; mt < 4; mt++) {
        #pragma unroll
        for (int nt = 0; nt < 8; nt++) {
            #pragma unroll
            for (int q = 0; q < 4; q++) {
                int gm = m0 + wr*64 + mt*16 + (lane >> 2) + ((q >= 2) ? 8 : 0);
                int gn = n0 + wc*64 + nt*8 + 2*(lane & 3) + (q & 1);
                float v = acc[mt][nt][q];
                if (EPI == EPI_PART) {
                    if (gn < N)
                        ((float*)Cv)[(size_t)blockIdx.z*TOK*PC + (size_t)gm*ldc + gn] = v;
                    continue;
                }
                v += bias[gn];
                if (EPI == EPI_SPLIT_SILU) {
                    float sv = v / (1.f + __expf(-v));
                    if (gn < Eq) ((__half*)Cv)[(size_t)gm*Eq + gn] = __float2half_rn(sv);
                    else         gate[(size_t)gm*Eq + gn - Eq]    = __float2half_rn(sv);
                } else if (EPI == EPI_SOFTPLUS) {
                    ((float*)Cv)[(size_t)gm*ldc + gn] = (v > 20.f) ? v : log1pf(__expf(v));
                } else { // EPI_RES
                    ((float*)Cv)[(size_t)gm*ldc + gn] = v + resid[(size_t)gm*ldc + gn];
                }
            }
        }
    }
}

// ---------------- chunked selective scan ----------------
#define LOG2E 1.4426950408889634f

__global__ void __launch_bounds__(256)
scan_p1(const float* __restrict__ A_log) {
    int gw    = blockIdx.x*8 + (threadIdx.x >> 5);
    int lane  = threadIdx.x & 31;
    int egrp  = gw & 127;
    int chunk = gw >> 7;
    int c = egrp*32 + lane;
    int b = c >> 11;
    int e = c & (Eq-1);
    int t0 = chunk * CT;

    float Aen[Nq];
    #pragma unroll
    for (int n = 0; n < Nq; n++)
        Aen[n] = -__expf(A_log[e*Nq + n]) * LOG2E;

    float h[Nq], ap[Nq];
    #pragma unroll
    for (int n = 0; n < Nq; n++) { h[n] = 0.f; ap[n] = 1.f; }

    const float*  dp = g_delta + ((size_t)b*Lq + t0)*Eq + e;
    const __half* up = g_u     + ((size_t)b*Lq + t0)*Eq + e;

    #pragma unroll 2
    for (int t = 0; t < CT; t++) {
        float d  = dp[(size_t)t*Eq];
        float xv = __half2float(up[(size_t)t*Eq]);
        float dx = d * xv;
        const float4* pB4 = (const float4*)(g_P + ((size_t)b*Lq + t0 + t)*PC + 64);
        #pragma unroll
        for (int q = 0; q < 4; q++) {
            float4 Bv = __ldg(pB4 + q);
            float bb[4] = {Bv.x, Bv.y, Bv.z, Bv.w};
            #pragma unroll
            for (int r = 0; r < 4; r++) {
                int n = q*4 + r;
                float da = exp2f(d * Aen[n]);
                ap[n] *= da;
                h[n] = fmaf(da, h[n], dx * bb[r]);
            }
        }
    }
    float4* apo = (float4*)(g_ap + ((size_t)chunk*NCHAN + c)*Nq);
    float4* co  = (float4*)(g_c  + ((size_t)chunk*NCHAN + c)*Nq);
    #pragma unroll
    for (int q = 0; q < 4; q++) {
        apo[q] = make_float4(ap[q*4], ap[q*4+1], ap[q*4+2], ap[q*4+3]);
        co[q]  = make_float4(h[q*4],  h[q*4+1],  h[q*4+2],  h[q*4+3]);
    }
}

__global__ void __launch_bounds__(256)
scan_p2() {
    int i = blockIdx.x*blockDim.x + threadIdx.x;
    if (i >= NCHAN*Nq) return;
    float hin = 0.f;
    #pragma unroll
    for (int k = 0; k < NCHUNK; k++) {
        size_t idx = (size_t)k*NCHAN*Nq + i;
        g_hin[idx] = hin;
        hin = g_ap[idx]*hin + g_c[idx];
    }
}

__global__ void __launch_bounds__(256)
scan_p3(const float* __restrict__ A_log, const float* __restrict__ Dv) {
    int gw    = blockIdx.x*8 + (threadIdx.x >> 5);
    int lane  = threadIdx.x & 31;
    int egrp  = gw & 127;
    int chunk = gw >> 7;
    int c = egrp*32 + lane;
    int b = c >> 11;
    int e = c & (Eq-1);
    int t0 = chunk * CT;

    float Aen[Nq];
    #pragma unroll
    for (int n = 0; n < Nq; n++)
        Aen[n] = -__expf(A_log[e*Nq + n]) * LOG2E;
    float De = Dv[e];

    float h[Nq];
    const float4* hi = (const float4*)(g_hin + ((size_t)chunk*NCHAN + c)*Nq);
    #pragma unroll
    for (int q = 0; q < 4; q++) {
        float4 v = hi[q];
        h[q*4] = v.x; h[q*4+1] = v.y; h[q*4+2] = v.z; h[q*4+3] = v.w;
    }

    const float*  dp = g_delta + ((size_t)b*Lq + t0)*Eq + e;
    const __half* up = g_u     + ((size_t)b*Lq + t0)*Eq + e;
    const __half* gp = g_gate  + ((size_t)b*Lq + t0)*Eq + e;
    __half*       yp = g_y     + ((size_t)b*Lq + t0)*Eq + e;

    #pragma unroll 2
    for (int t = 0; t < CT; t++) {
        float d  = dp[(size_t)t*Eq];
        float xv = __half2float(up[(size_t)t*Eq]);
        float dx = d * xv;
        const float4* pB4 = (const float4*)(g_P + ((size_t)b*Lq + t0 + t)*PC + 64);
        float y = 0.f;
        #pragma unroll
        for (int q = 0; q < 4; q++) {
            float4 Bv = __ldg(pB4 + q);
            float4 Cv = __ldg(pB4 + 4 + q);
            float bb[4] = {Bv.x, Bv.y, Bv.z, Bv.w};
            float cc[4] = {Cv.x, Cv.y, Cv.z, Cv.w};
            #pragma unroll
            for (int r = 0; r < 4; r++) {
                int n = q*4 + r;
                float da = exp2f(d * Aen[n]);
                h[n] = fmaf(da, h[n], dx * bb[r]);
                y = fmaf(cc[r], h[n], y);
            }
        }
        float g = __half2float(gp[(size_t)t*Eq]);
        yp[(size_t)t*Eq] = __float2half_rn(fmaf(xv, De, y) * g);
    }
}

// ---------------- launch ----------------
extern "C" void kernel_launch(void* const* d_in, const int* in_sizes, int n_in,
                              void* d_out, int out_size) {
    const float* x       = (const float*)d_in[0];
    const float* lng     = (const float*)d_in[1];
    const float* lnb     = (const float*)d_in[2];
    const float* W_in    = (const float*)d_in[3];
    const float* b_in    = (const float*)d_in[4];
    const float* W_delta = (const float*)d_in[5];
    const float* b_delta = (const float*)d_in[6];
    const float* W_dt    = (const float*)d_in[7];
    const float* b_dt    = (const float*)d_in[8];
    const float* W_B     = (const float*)d_in[9];
    const float* b_B     = (const float*)d_in[10];
    const float* W_C     = (const float*)d_in[11];
    const float* b_C     = (const float*)d_in[12];
    const float* A_log   = (const float*)d_in[13];
    const float* Dv      = (const float*)d_in[14];
    const float* W_out   = (const float*)d_in[15];
    const float* b_out   = (const float*)d_in[16];
    float* out = (float*)d_out;

    void *p_xn, *p_u, *p_gate, *p_P, *p_Ph, *p_Ppart, *p_delta, *p_y;
    void *p_WcatT, *p_WtIn, *p_WtDt, *p_WtOut;
    cudaGetSymbolAddress(&p_xn,    g_xn);
    cudaGetSymbolAddress(&p_u,     g_u);
    cudaGetSymbolAddress(&p_gate,  g_gate);
    cudaGetSymbolAddress(&p_P,     g_P);
    cudaGetSymbolAddress(&p_Ph,    g_Ph);
    cudaGetSymbolAddress(&p_Ppart, g_Ppart);
    cudaGetSymbolAddress(&p_delta, g_delta);
    cudaGetSymbolAddress(&p_y,     g_y);
    cudaGetSymbolAddress(&p_WcatT, g_WcatT);
    cudaGetSymbolAddress(&p_WtIn,  g_WtIn);
    cudaGetSymbolAddress(&p_WtDt,  g_WtDt);
    cudaGetSymbolAddress(&p_WtOut, g_WtOut);

    static bool attr_done = false;
    if (!attr_done) {
        cudaFuncSetAttribute(gemm_h<EPI_SPLIT_SILU>, cudaFuncAttributeMaxDynamicSharedMemorySize, H_SMEM);
        cudaFuncSetAttribute(gemm_h<EPI_SOFTPLUS>,   cudaFuncAttributeMaxDynamicSharedMemorySize, H_SMEM);
        cudaFuncSetAttribute(gemm_h<EPI_RES>,        cudaFuncAttributeMaxDynamicSharedMemorySize, H_SMEM);
        cudaFuncSetAttribute(gemm_h<EPI_PART>,       cudaFuncAttributeMaxDynamicSharedMemorySize, H_SMEM);
        attr_done = true;
    }

    // prep: fp16 transposed weights + packed proj weight
    transpose_h<<<dim3(2*Eq/32, Hq/32), dim3(32,8)>>>(W_in,  (__half*)p_WtIn,  Hq, 2*Eq);
    transpose_h<<<dim3(Hq/32,   Eq/32), dim3(32,8)>>>(W_out, (__half*)p_WtOut, Eq, Hq);
    transpose_h<<<dim3(Eq/32,   Rq/32), dim3(32,8)>>>(W_dt,  (__half*)p_WtDt,  Rq, Eq);
    pack_kernel<<<(PCP*Eq + 255)/256, 256>>>(W_delta, W_B, W_C, b_delta, b_B, b_C);
    // LayerNorm -> fp16 xn
    ln_kernel<<<TOK, 256>>>(x, lng, lnb);
    // GEMM1: xn @ W_in -> silu(u), silu(gate)
    gemm_h<EPI_SPLIT_SILU><<<dim3(2*Eq/128, TOK/128), 128, H_SMEM>>>(
        (const __half*)p_xn, Hq, (const __half*)p_WtIn, Hq, b_in,
        p_u, Eq, nullptr, (__half*)p_gate, TOK, 2*Eq, Hq, Hq);
    // P partials = u @ Wcat (split-K), reduce (+fp16 copy of delta part)
    gemm_h<EPI_PART><<<dim3(1, TOK/128, KSPLIT), 128, H_SMEM>>>(
        (const __half*)p_u, Eq, (const __half*)p_WcatT, Eq, nullptr,
        p_Ppart, PC, nullptr, nullptr, TOK, PC, Eq, Eq/KSPLIT);
    reduceP_kernel<<<(TOK*PC + 255)/256, 256>>>();
    // delta = softplus(Ph @ W_dt)
    gemm_h<EPI_SOFTPLUS><<<dim3(Eq/128, TOK/128), 128, H_SMEM>>>(
        (const __half*)p_Ph, 64, (const __half*)p_WtDt, Rq, b_dt,
        p_delta, Eq, nullptr, nullptr, TOK, Eq, Rq, Rq);
    // chunked selective scan
    scan_p1<<<(NCHAN/32)*NCHUNK/8, 256>>>(A_log);
    scan_p2<<<(NCHAN*Nq + 255)/256, 256>>>();
    scan_p3<<<(NCHAN/32)*NCHUNK/8, 256>>>(A_log, Dv);
    // out = y @ W_out + b_out + residual
    gemm_h<EPI_RES><<<dim3(Hq/128, TOK/128), 128, H_SMEM>>>(
        (const __half*)p_y, Eq, (const __half*)p_WtOut, Eq, b_out,
        out, Hq, x, nullptr, TOK, Hq, Eq, Eq);
}

// round 10
// speedup vs baseline: 7.6936x; 1.0115x over previous
#include <cuda_runtime.h>
#include <cuda_fp16.h>
#include <math.h>
#include <stdint.h>

// Problem constants
#define Bq   2
#define Lq   2048
#define Hq   1024
#define Eq   2048
#define Nq   16
#define Rq   64
#define TOK  (Bq*Lq)        // 4096 tokens
#define PC   96             // packed proj cols: 64 (delta) + 16 (B) + 16 (C)
#define PCP  128            // padded N for P-GEMM
#define KSPLIT 8
#define NCHUNK 32           // scan chunks
#define CT    (Lq/NCHUNK)   // 64 timesteps per chunk
#define NCHAN (Bq*Eq)       // 4096 channels

// ---------------- device scratch (allocation-free) ----------------
__device__ __align__(16) __half g_xn[TOK*Hq];      // layernormed input (fp16)
__device__ __align__(16) __half g_u[TOK*Eq];       // silu(u) fp16
__device__ __align__(16) __half g_gate[TOK*Eq];    // silu(gate) fp16
__device__ __align__(16) __half g_y[TOK*Eq];       // scan output fp16
__device__ __align__(16) float  g_P[TOK*PC];       // [delta_proj(64) | B(16) | C(16)] f32
__device__ __align__(16) __half g_Ph[TOK*64];      // delta-proj part, fp16 (GEMM input)
__device__ __align__(16) float  g_Ppart[KSPLIT*TOK*PC];
__device__ __align__(16) float  g_delta[TOK*Eq];   // softplus delta f32
__device__ __align__(16) __half g_WcatT[PCP*Eq];   // [delta|B|C]^T padded, fp16
__device__ float g_bcat[PC];
__device__ __align__(16) __half g_WtIn[2*Eq*Hq];   // W_in^T  [4096][1024] fp16
__device__ __align__(16) __half g_WtDt[Eq*Rq];     // W_dt^T  [2048][64]   fp16
__device__ __align__(16) __half g_WtOut[Hq*Eq];    // W_out^T [1024][2048] fp16
// chunked-scan state: [chunk][chan][n]
__device__ __align__(16) float g_ap [NCHUNK*NCHAN*Nq];
__device__ __align__(16) float g_c  [NCHUNK*NCHAN*Nq];
__device__ __align__(16) float g_hin[NCHUNK*NCHAN*Nq];

__device__ __forceinline__ uint32_t sptr(const void* p) {
    return (uint32_t)__cvta_generic_to_shared(p);
}

// ---------------- LayerNorm (writes fp16 xn) ----------------
__global__ void ln_kernel(const float* __restrict__ x,
                          const float* __restrict__ gamma,
                          const float* __restrict__ beta) {
    int m = blockIdx.x;
    const float* row = x + (size_t)m*Hq;
    float s = 0.f, s2 = 0.f;
    for (int i = threadIdx.x; i < Hq; i += blockDim.x) {
        float v = row[i]; s += v; s2 += v*v;
    }
    __shared__ float sh[64];
    for (int o = 16; o; o >>= 1) {
        s  += __shfl_xor_sync(~0u, s,  o);
        s2 += __shfl_xor_sync(~0u, s2, o);
    }
    int wid = threadIdx.x >> 5, lane = threadIdx.x & 31;
    if (lane == 0) { sh[wid] = s; sh[32+wid] = s2; }
    __syncthreads();
    if (wid == 0) {
        int nw = blockDim.x >> 5;
        s  = (lane < nw) ? sh[lane]    : 0.f;
        s2 = (lane < nw) ? sh[32+lane] : 0.f;
        for (int o = 16; o; o >>= 1) {
            s  += __shfl_xor_sync(~0u, s,  o);
            s2 += __shfl_xor_sync(~0u, s2, o);
        }
        if (lane == 0) { sh[0] = s; sh[1] = s2; }
    }
    __syncthreads();
    float mu  = sh[0] * (1.f/Hq);
    float var = sh[1] * (1.f/Hq) - mu*mu;
    float inv = rsqrtf(var + 1e-5f);
    for (int i = threadIdx.x; i < Hq; i += blockDim.x) {
        g_xn[(size_t)m*Hq + i] = __float2half_rn((row[i]-mu)*inv*gamma[i] + beta[i]);
    }
}

// ---------------- tiled transpose to fp16: dst[c][r] = h(src[r][c]) ----------
__global__ void transpose_h(const float* __restrict__ src, __half* __restrict__ dst,
                            int R, int Cc) {
    __shared__ float t[32][33];
    int c0 = blockIdx.x*32, r0 = blockIdx.y*32;
    for (int i = threadIdx.y; i < 32; i += 8)
        t[i][threadIdx.x] = src[(size_t)(r0+i)*Cc + c0 + threadIdx.x];
    __syncthreads();
    for (int i = threadIdx.y; i < 32; i += 8)
        dst[(size_t)(c0+i)*R + r0 + threadIdx.x] = __float2half_rn(t[threadIdx.x][i]);
}

// ---------------- pack W_delta|W_B|W_C transposed+padded, fp16 --------------
__global__ void pack_kernel(const float* __restrict__ Wd, const float* __restrict__ Wb,
                            const float* __restrict__ Wc, const float* __restrict__ bd,
                            const float* __restrict__ bb, const float* __restrict__ bc) {
    int i = blockIdx.x*blockDim.x + threadIdx.x;
    if (i < PCP*Eq) {
        int c = i / Eq, k = i % Eq;
        float v = 0.f;
        if (c < 64)      v = Wd[k*64 + c];
        else if (c < 80) v = Wb[k*16 + (c-64)];
        else if (c < 96) v = Wc[k*16 + (c-80)];
        g_WcatT[i] = __float2half_rn(v);
    }
    if (i < PC) {
        g_bcat[i] = (i < 64) ? bd[i] : ((i < 80) ? bb[i-64] : bc[i-80]);
    }
}

// ---------------- split-K reduction for P (f32 + fp16 delta part) -----------
__global__ void reduceP_kernel() {
    int i = blockIdx.x*blockDim.x + threadIdx.x;
    if (i >= TOK*PC) return;
    int c = i % PC, m = i / PC;
    float s = g_bcat[c];
    #pragma unroll
    for (int z = 0; z < KSPLIT; z++) s += g_Ppart[(size_t)z*TOK*PC + i];
    g_P[i] = s;
    if (c < 64) g_Ph[(size_t)m*64 + c] = __float2half_rn(s);
}

// ======== fp16 m16n8k16 GEMM, 8 warps, 64x32 warptiles, ldmatrix ============
enum { EPI_SPLIT_SILU = 1, EPI_SOFTPLUS = 2, EPI_RES = 3, EPI_PART = 4 };

#define MMA_F16(c0,c1,c2,c3,a0,a1,a2,a3,b0,b1) \
    asm volatile("mma.sync.aligned.m16n8k16.row.col.f32.f16.f16.f32 " \
                 "{%0,%1,%2,%3},{%4,%5,%6,%7},{%8,%9},{%0,%1,%2,%3};" \
                 : "+f"(c0),"+f"(c1),"+f"(c2),"+f"(c3) \
                 : "r"(a0),"r"(a1),"r"(a2),"r"(a3),"r"(b0),"r"(b1))

#define LDSM_X4(r0,r1,r2,r3,addr) \
    asm volatile("ldmatrix.sync.aligned.m8n8.x4.shared.b16 {%0,%1,%2,%3}, [%4];" \
                 : "=r"(r0),"=r"(r1),"=r"(r2),"=r"(r3) : "r"(addr))

template<int N> __device__ __forceinline__ void cp_wait() {
    asm volatile("cp.async.wait_group %0;" :: "n"(N));
}
__device__ __forceinline__ void cp_commit() {
    asm volatile("cp.async.commit_group;" ::);
}

#define HBM 128
#define HBN 128
#define HBK 32
#define HSTAGE 4
#define HLD 40                      // halves per row (32 + 8 pad) = 80 bytes
#define HSTG (HBM*HLD)              // halves per stage tile (5120)
#define H_SMEM (HSTAGE*HSTG*2*2)    // A + B regions, bytes (81920)

template<int EPI>
__global__ void __launch_bounds__(256, 2)
gemm_h(const __half* __restrict__ A, int lda,
       const __half* __restrict__ Bt, int ldb,    // [N][K] K-major
       const float* __restrict__ bias,
       void* __restrict__ Cv, int ldc,
       const float* __restrict__ resid,           // residual (RES)
       __half* __restrict__ gate,                 // gate out (SPLIT_SILU)
       int M, int N, int K, int Kchunk)
{
    extern __shared__ __half smh[];
    __half* Asm = smh;
    __half* Bsm = smh + HSTAGE*HSTG;
    const uint32_t aBase = sptr(Asm);
    const uint32_t bBase = sptr(Bsm);

    const int tid  = threadIdx.x;
    const int lane = tid & 31;
    const int warp = tid >> 5;
    const int wr   = warp & 1;          // 2 x 64 rows
    const int wc   = warp >> 1;         // 4 x 32 cols
    const int m0   = blockIdx.y * HBM;
    const int n0   = blockIdx.x * HBN;
    const int Koff = blockIdx.z * Kchunk;

    // ldmatrix per-lane base offsets (halves; *2 for bytes at use site)
    const uint32_t aRow = wr*64 + (lane & 15);
    const uint32_t aCol = (lane >> 4) * 8;
    // B non-trans: lanes 0-7 rows n0..7 @k0 | 8-15 @k0+8 | 16-23 rows n8..15 @k0 | 24-31 @k0+8
    const uint32_t bRow = wc*32 + (lane & 7) + ((lane >> 4) << 3);
    const uint32_t bCol = ((lane >> 3) & 1) * 8;

    auto issue = [&](int it, int buf) {
        int k0 = Koff + it * HBK;
        #pragma unroll
        for (int j = 0; j < 2; j++) {
            int id = tid + j*256;
            int row = id >> 2, slot = id & 3;
            const __half* as = A  + (size_t)(m0 + row)*lda + k0 + slot*8;
            const __half* bs = Bt + (size_t)(n0 + row)*ldb + k0 + slot*8;
            asm volatile("cp.async.ca.shared.global [%0], [%1], 16;\n"
                         :: "r"(aBase + buf*(HSTG*2) + row*80 + slot*16), "l"(as));
            asm volatile("cp.async.ca.shared.global [%0], [%1], 16;\n"
                         :: "r"(bBase + buf*(HSTG*2) + row*80 + slot*16), "l"(bs));
        }
    };

    float acc[4][4][4];
    #pragma unroll
    for (int i = 0; i < 4; i++)
        #pragma unroll
        for (int j = 0; j < 4; j++)
            #pragma unroll
            for (int k = 0; k < 4; k++) acc[i][j][k] = 0.f;

    const int nIter = Kchunk / HBK;
    #pragma unroll
    for (int s = 0; s < HSTAGE-1; s++) {
        if (s < nIter) issue(s, s);
        cp_commit();
    }

    for (int it = 0; it < nIter; it++) {
        cp_wait<HSTAGE-2>();
        __syncthreads();
        int nx = it + HSTAGE - 1;
        if (nx < nIter) issue(nx, nx & (HSTAGE-1));
        cp_commit();

        int buf = it & (HSTAGE-1);
        uint32_t aB = aBase + buf*(HSTG*2);
        uint32_t bB = bBase + buf*(HSTG*2);

        #pragma unroll
        for (int kk = 0; kk < 2; kk++) {
            uint32_t af[4][4], bf[4][2];
            #pragma unroll
            for (int mt = 0; mt < 4; mt++) {
                uint32_t ad = aB + ((aRow + mt*16)*HLD + kk*16 + aCol)*2;
                LDSM_X4(af[mt][0], af[mt][1], af[mt][2], af[mt][3], ad);
            }
            #pragma unroll
            for (int ntp = 0; ntp < 2; ntp++) {
                uint32_t bd = bB + ((bRow + ntp*16)*HLD + kk*16 + bCol)*2;
                LDSM_X4(bf[2*ntp][0], bf[2*ntp][1], bf[2*ntp+1][0], bf[2*ntp+1][1], bd);
            }
            #pragma unroll
            for (int mt = 0; mt < 4; mt++)
                #pragma unroll
                for (int nt = 0; nt < 4; nt++)
                    MMA_F16(acc[mt][nt][0], acc[mt][nt][1], acc[mt][nt][2], acc[mt][nt][3],
                            af[mt][0], af[mt][1], af[mt][2], af[mt][3],
                            bf[nt][0], bf[nt][1]);
        }
    }

    // epilogue: pair (q0,q1)/(q2,q3) -> column-adjacent vector stores
    #pragma unroll
    for (int mt = 0; mt < 4; mt++) {
        #pragma unroll
        for (int nt = 0; nt < 4; nt++) {
            #pragma unroll
            for (int half = 0; half < 2; half++) {
                int gm = m0 + wr*64 + mt*16 + (lane >> 2) + half*8;
                int gn = n0 + wc*32 + nt*8 + 2*(lane & 3);
                float v0 = acc[mt][nt][half*2 + 0];
                float v1 = acc[mt][nt][half*2 + 1];
                if (EPI == EPI_PART) {
                    if (gn < N) {
                        float* dst = (float*)Cv + (size_t)blockIdx.z*TOK*PC + (size_t)gm*ldc + gn;
                        dst[0] = v0;
                        if (gn + 1 < N) dst[1] = v1;
                    }
                    continue;
                }
                v0 += bias[gn]; v1 += bias[gn+1];
                if (EPI == EPI_SPLIT_SILU) {
                    float s0 = v0 / (1.f + __expf(-v0));
                    float s1 = v1 / (1.f + __expf(-v1));
                    __half2 hv = __floats2half2_rn(s0, s1);
                    if (gn < Eq) *(__half2*)((__half*)Cv + (size_t)gm*Eq + gn) = hv;
                    else         *(__half2*)(gate + (size_t)gm*Eq + gn - Eq)  = hv;
                } else if (EPI == EPI_SOFTPLUS) {
                    float2 f2;
                    f2.x = (v0 > 20.f) ? v0 : log1pf(__expf(v0));
                    f2.y = (v1 > 20.f) ? v1 : log1pf(__expf(v1));
                    *(float2*)((float*)Cv + (size_t)gm*ldc + gn) = f2;
                } else { // EPI_RES
                    const float2 r2 = *(const float2*)(resid + (size_t)gm*ldc + gn);
                    float2 f2; f2.x = v0 + r2.x; f2.y = v1 + r2.y;
                    *(float2*)((float*)Cv + (size_t)gm*ldc + gn) = f2;
                }
            }
        }
    }
}

// ---------------- chunked selective scan ----------------
#define LOG2E 1.4426950408889634f

__global__ void __launch_bounds__(256)
scan_p1(const float* __restrict__ A_log) {
    int gw    = blockIdx.x*8 + (threadIdx.x >> 5);
    int lane  = threadIdx.x & 31;
    int egrp  = gw & 127;
    int chunk = gw >> 7;
    int c = egrp*32 + lane;
    int b = c >> 11;
    int e = c & (Eq-1);
    int t0 = chunk * CT;

    float Aen[Nq];
    #pragma unroll
    for (int n = 0; n < Nq; n++)
        Aen[n] = -__expf(A_log[e*Nq + n]) * LOG2E;

    float h[Nq], ap[Nq];
    #pragma unroll
    for (int n = 0; n < Nq; n++) { h[n] = 0.f; ap[n] = 1.f; }

    const float*  dp = g_delta + ((size_t)b*Lq + t0)*Eq + e;
    const __half* up = g_u     + ((size_t)b*Lq + t0)*Eq + e;

    #pragma unroll 2
    for (int t = 0; t < CT; t++) {
        float d  = dp[(size_t)t*Eq];
        float xv = __half2float(up[(size_t)t*Eq]);
        float dx = d * xv;
        const float4* pB4 = (const float4*)(g_P + ((size_t)b*Lq + t0 + t)*PC + 64);
        #pragma unroll
        for (int q = 0; q < 4; q++) {
            float4 Bv = __ldg(pB4 + q);
            float bb[4] = {Bv.x, Bv.y, Bv.z, Bv.w};
            #pragma unroll
            for (int r = 0; r < 4; r++) {
                int n = q*4 + r;
                float da = exp2f(d * Aen[n]);
                ap[n] *= da;
                h[n] = fmaf(da, h[n], dx * bb[r]);
            }
        }
    }
    float4* apo = (float4*)(g_ap + ((size_t)chunk*NCHAN + c)*Nq);
    float4* co  = (float4*)(g_c  + ((size_t)chunk*NCHAN + c)*Nq);
    #pragma unroll
    for (int q = 0; q < 4; q++) {
        apo[q] = make_float4(ap[q*4], ap[q*4+1], ap[q*4+2], ap[q*4+3]);
        co[q]  = make_float4(h[q*4],  h[q*4+1],  h[q*4+2],  h[q*4+3]);
    }
}

__global__ void __launch_bounds__(256)
scan_p2() {
    int i = blockIdx.x*blockDim.x + threadIdx.x;
    if (i >= NCHAN*Nq) return;
    float hin = 0.f;
    #pragma unroll
    for (int k = 0; k < NCHUNK; k++) {
        size_t idx = (size_t)k*NCHAN*Nq + i;
        g_hin[idx] = hin;
        hin = g_ap[idx]*hin + g_c[idx];
    }
}

__global__ void __launch_bounds__(256)
scan_p3(const float* __restrict__ A_log, const float* __restrict__ Dv) {
    int gw    = blockIdx.x*8 + (threadIdx.x >> 5);
    int lane  = threadIdx.x & 31;
    int egrp  = gw & 127;
    int chunk = gw >> 7;
    int c = egrp*32 + lane;
    int b = c >> 11;
    int e = c & (Eq-1);
    int t0 = chunk * CT;

    float Aen[Nq];
    #pragma unroll
    for (int n = 0; n < Nq; n++)
        Aen[n] = -__expf(A_log[e*Nq + n]) * LOG2E;
    float De = Dv[e];

    float h[Nq];
    const float4* hi = (const float4*)(g_hin + ((size_t)chunk*NCHAN + c)*Nq);
    #pragma unroll
    for (int q = 0; q < 4; q++) {
        float4 v = hi[q];
        h[q*4] = v.x; h[q*4+1] = v.y; h[q*4+2] = v.z; h[q*4+3] = v.w;
    }

    const float*  dp = g_delta + ((size_t)b*Lq + t0)*Eq + e;
    const __half* up = g_u     + ((size_t)b*Lq + t0)*Eq + e;
    const __half* gp = g_gate  + ((size_t)b*Lq + t0)*Eq + e;
    __half*       yp = g_y     + ((size_t)b*Lq + t0)*Eq + e;

    #pragma unroll 2
    for (int t = 0; t < CT; t++) {
        float d  = dp[(size_t)t*Eq];
        float xv = __half2float(up[(size_t)t*Eq]);
        float dx = d * xv;
        const float4* pB4 = (const float4*)(g_P + ((size_t)b*Lq + t0 + t)*PC + 64);
        float y = 0.f;
        #pragma unroll
        for (int q = 0; q < 4; q++) {
            float4 Bv = __ldg(pB4 + q);
            float4 Cv = __ldg(pB4 + 4 + q);
            float bb[4] = {Bv.x, Bv.y, Bv.z, Bv.w};
            float cc[4] = {Cv.x, Cv.y, Cv.z, Cv.w};
            #pragma unroll
            for (int r = 0; r < 4; r++) {
                int n = q*4 + r;
                float da = exp2f(d * Aen[n]);
                h[n] = fmaf(da, h[n], dx * bb[r]);
                y = fmaf(cc[r], h[n], y);
            }
        }
        float g = __half2float(gp[(size_t)t*Eq]);
        yp[(size_t)t*Eq] = __float2half_rn(fmaf(xv, De, y) * g);
    }
}

// ---------------- launch ----------------
extern "C" void kernel_launch(void* const* d_in, const int* in_sizes, int n_in,
                              void* d_out, int out_size) {
    const float* x       = (const float*)d_in[0];
    const float* lng     = (const float*)d_in[1];
    const float* lnb     = (const float*)d_in[2];
    const float* W_in    = (const float*)d_in[3];
    const float* b_in    = (const float*)d_in[4];
    const float* W_delta = (const float*)d_in[5];
    const float* b_delta = (const float*)d_in[6];
    const float* W_dt    = (const float*)d_in[7];
    const float* b_dt    = (const float*)d_in[8];
    const float* W_B     = (const float*)d_in[9];
    const float* b_B     = (const float*)d_in[10];
    const float* W_C     = (const float*)d_in[11];
    const float* b_C     = (const float*)d_in[12];
    const float* A_log   = (const float*)d_in[13];
    const float* Dv      = (const float*)d_in[14];
    const float* W_out   = (const float*)d_in[15];
    const float* b_out   = (const float*)d_in[16];
    float* out = (float*)d_out;

    void *p_xn, *p_u, *p_gate, *p_P, *p_Ph, *p_Ppart, *p_delta, *p_y;
    void *p_WcatT, *p_WtIn, *p_WtDt, *p_WtOut;
    cudaGetSymbolAddress(&p_xn,    g_xn);
    cudaGetSymbolAddress(&p_u,     g_u);
    cudaGetSymbolAddress(&p_gate,  g_gate);
    cudaGetSymbolAddress(&p_P,     g_P);
    cudaGetSymbolAddress(&p_Ph,    g_Ph);
    cudaGetSymbolAddress(&p_Ppart, g_Ppart);
    cudaGetSymbolAddress(&p_delta, g_delta);
    cudaGetSymbolAddress(&p_y,     g_y);
    cudaGetSymbolAddress(&p_WcatT, g_WcatT);
    cudaGetSymbolAddress(&p_WtIn,  g_WtIn);
    cudaGetSymbolAddress(&p_WtDt,  g_WtDt);
    cudaGetSymbolAddress(&p_WtOut, g_WtOut);

    static bool attr_done = false;
    if (!attr_done) {
        cudaFuncSetAttribute(gemm_h<EPI_SPLIT_SILU>, cudaFuncAttributeMaxDynamicSharedMemorySize, H_SMEM);
        cudaFuncSetAttribute(gemm_h<EPI_SOFTPLUS>,   cudaFuncAttributeMaxDynamicSharedMemorySize, H_SMEM);
        cudaFuncSetAttribute(gemm_h<EPI_RES>,        cudaFuncAttributeMaxDynamicSharedMemorySize, H_SMEM);
        cudaFuncSetAttribute(gemm_h<EPI_PART>,       cudaFuncAttributeMaxDynamicSharedMemorySize, H_SMEM);
        attr_done = true;
    }

    // prep: fp16 transposed weights + packed proj weight
    transpose_h<<<dim3(2*Eq/32, Hq/32), dim3(32,8)>>>(W_in,  (__half*)p_WtIn,  Hq, 2*Eq);
    transpose_h<<<dim3(Hq/32,   Eq/32), dim3(32,8)>>>(W_out, (__half*)p_WtOut, Eq, Hq);
    transpose_h<<<dim3(Eq/32,   Rq/32), dim3(32,8)>>>(W_dt,  (__half*)p_WtDt,  Rq, Eq);
    pack_kernel<<<(PCP*Eq + 255)/256, 256>>>(W_delta, W_B, W_C, b_delta, b_B, b_C);
    // LayerNorm -> fp16 xn
    ln_kernel<<<TOK, 256>>>(x, lng, lnb);
    // GEMM1: xn @ W_in -> silu(u), silu(gate)
    gemm_h<EPI_SPLIT_SILU><<<dim3(2*Eq/128, TOK/128), 256, H_SMEM>>>(
        (const __half*)p_xn, Hq, (const __half*)p_WtIn, Hq, b_in,
        p_u, Eq, nullptr, (__half*)p_gate, TOK, 2*Eq, Hq, Hq);
    // P partials = u @ Wcat (split-K), reduce (+fp16 copy of delta part)
    gemm_h<EPI_PART><<<dim3(1, TOK/128, KSPLIT), 256, H_SMEM>>>(
        (const __half*)p_u, Eq, (const __half*)p_WcatT, Eq, nullptr,
        p_Ppart, PC, nullptr, nullptr, TOK, PC, Eq, Eq/KSPLIT);
    reduceP_kernel<<<(TOK*PC + 255)/256, 256>>>();
    // delta = softplus(Ph @ W_dt)
    gemm_h<EPI_SOFTPLUS><<<dim3(Eq/128, TOK/128), 256, H_SMEM>>>(
        (const __half*)p_Ph, 64, (const __half*)p_WtDt, Rq, b_dt,
        p_delta, Eq, nullptr, nullptr, TOK, Eq, Rq, Rq);
    // chunked selective scan
    scan_p1<<<(NCHAN/32)*NCHUNK/8, 256>>>(A_log);
    scan_p2<<<(NCHAN*Nq + 255)/256, 256>>>();
    scan_p3<<<(NCHAN/32)*NCHUNK/8, 256>>>(A_log, Dv);
    // out = y @ W_out + b_out + residual
    gemm_h<EPI_RES><<<dim3(Hq/128, TOK/128), 256, H_SMEM>>>(
        (const __half*)p_y, Eq, (const __half*)p_WtOut, Eq, b_out,
        out, Hq, x, nullptr, TOK, Hq, Eq, Eq);
}